// round 1
// baseline (speedup 1.0000x reference)
#include <cuda_runtime.h>
#include <cuda_bf16.h>
#include <math.h>

// Problem constants (SubgraphGNN): N=30000, E=480000, D=128, R=16, H=4, DH=32, L=3
#define MAXN 30000
#define MAXE 480000
#define D 128
#define R 16
#define NH 4
#define DH 32
#define NL 3

// ---------------- scratch (static device globals; no cudaMalloc allowed) ----
__device__ float g_ht[(long)MAXN * (R * D)];      // [N, R*D] per-relation transformed feats
__device__ float g_hcat[(long)MAXN * (2 * D)];    // [N, 256]: [:,0:128]=h_rel, [:,128:256]=h_gat
__device__ float g_h[(long)MAXN * D];             // current node features between layers
__device__ float g_z[(long)MAXN * D];             // z = h @ W_gat  (reused as hc buffer)
__device__ float g_el[MAXN * NH];
__device__ float g_er[MAXN * NH];
__device__ float g_m[MAXN * NH];
__device__ float g_den[MAXN * NH];
__device__ float g_ebuf[MAXE * NH];
__device__ float g_twsum;

// ---------------- helpers ---------------------------------------------------
__device__ __forceinline__ void red_add_v4(float* p, float x, float y, float z, float w) {
#if __CUDA_ARCH__ >= 900
    asm volatile("red.global.add.v4.f32 [%0], {%1, %2, %3, %4};"
                 :: "l"(p), "f"(x), "f"(y), "f"(z), "f"(w) : "memory");
#else
    atomicAdd(p + 0, x); atomicAdd(p + 1, y); atomicAdd(p + 2, z); atomicAdd(p + 3, w);
#endif
}

__device__ __forceinline__ void atomicMaxF(float* addr, float val) {
    if (val >= 0.0f) {
        atomicMax((int*)addr, __float_as_int(val));
    } else {
        atomicMin((unsigned int*)addr, (unsigned int)__float_as_int(val));
    }
}

// ---------------- SGEMM: C[M,128] = A[M,K] * B[K,128] (+epilogue) -----------
// BM=128, BN=128, BK=8, 256 threads, 8x8 per-thread tile.
// EPI: 0 = none(+opt bias), 2 = bias+relu, 3 = temporal gate (layer-0 only)
template <int EPI>
__global__ __launch_bounds__(256)
void sgemm_k(const float* __restrict__ A, int lda,
             const float* __restrict__ Bg, int ldb, long bstride_y,
             float* __restrict__ Cg, int ldc, long cstride_y,
             int M, int K,
             const float* __restrict__ bias,
             const float* __restrict__ gate_wlast,
             const float* __restrict__ tw_sum, float inv_E)
{
    const float* B = Bg + (long)blockIdx.y * bstride_y;
    float*       C = Cg + (long)blockIdx.y * cstride_y;

    __shared__ float As[8][128];
    __shared__ float Bs[8][128];

    const int tid  = threadIdx.x;
    const int m0   = blockIdx.x * 128;
    const int trow = tid / 16;          // 0..15
    const int tcol = tid % 16;          // 0..15

    const int arow  = tid >> 1;         // 0..127
    const int akoff = (tid & 1) * 4;    // 0 or 4
    const int bk    = tid >> 5;         // 0..7
    const int bn    = (tid & 31) * 4;   // 0..124

    float acc[8][8];
#pragma unroll
    for (int i = 0; i < 8; i++)
#pragma unroll
        for (int j = 0; j < 8; j++) acc[i][j] = 0.0f;

    for (int k0 = 0; k0 < K; k0 += 8) {
        float4 av = make_float4(0.f, 0.f, 0.f, 0.f);
        const int gm = m0 + arow;
        if (gm < M) av = *(const float4*)(A + (long)gm * lda + k0 + akoff);
        As[akoff + 0][arow] = av.x;
        As[akoff + 1][arow] = av.y;
        As[akoff + 2][arow] = av.z;
        As[akoff + 3][arow] = av.w;

        float4 bv = *(const float4*)(B + (long)(k0 + bk) * ldb + bn);
        *(float4*)&Bs[bk][bn] = bv;

        __syncthreads();
#pragma unroll
        for (int k = 0; k < 8; k++) {
            float4 a0 = *(float4*)&As[k][trow * 8];
            float4 a1 = *(float4*)&As[k][trow * 8 + 4];
            float4 b0 = *(float4*)&Bs[k][tcol * 8];
            float4 b1 = *(float4*)&Bs[k][tcol * 8 + 4];
            float ar[8] = {a0.x, a0.y, a0.z, a0.w, a1.x, a1.y, a1.z, a1.w};
            float br[8] = {b0.x, b0.y, b0.z, b0.w, b1.x, b1.y, b1.z, b1.w};
#pragma unroll
            for (int i = 0; i < 8; i++)
#pragma unroll
                for (int j = 0; j < 8; j++)
                    acc[i][j] = fmaf(ar[i], br[j], acc[i][j]);
        }
        __syncthreads();
    }

    float twm = 0.0f;
    if (EPI == 3) twm = tw_sum[0] * inv_E;

#pragma unroll
    for (int i = 0; i < 8; i++) {
        const int gm = m0 + trow * 8 + i;
        if (gm >= M) continue;
#pragma unroll
        for (int j = 0; j < 8; j++) {
            const int n = tcol * 8 + j;
            float v = acc[i][j];
            if (bias) v += bias[n];
            if (EPI == 2) v = fmaxf(v, 0.0f);
            if (EPI == 3) {
                float g = v + twm * gate_wlast[n];
                g = 1.0f / (1.0f + expf(-g));
                float hc = A[(long)gm * lda + n];   // A IS hc here (lda==128)
                v = fmaxf(hc * g, 0.0f);
            }
            C[(long)gm * ldc + n] = v;
        }
    }
}

// ---------------- small kernels ---------------------------------------------
__global__ void zero_scalar_k(float* p) { *p = 0.0f; }

__global__ void reduce_sum_k(const float* __restrict__ x, float* out, int n) {
    float s = 0.0f;
    for (int i = blockIdx.x * blockDim.x + threadIdx.x; i < n; i += gridDim.x * blockDim.x)
        s += x[i];
#pragma unroll
    for (int o = 16; o > 0; o >>= 1) s += __shfl_xor_sync(0xFFFFFFFFu, s, o);
    __shared__ float ws[8];
    if ((threadIdx.x & 31) == 0) ws[threadIdx.x >> 5] = s;
    __syncthreads();
    if (threadIdx.x < 32) {
        s = (threadIdx.x < (blockDim.x >> 5)) ? ws[threadIdx.x] : 0.0f;
#pragma unroll
        for (int o = 4; o > 0; o >>= 1) s += __shfl_xor_sync(0xFFFFFFFFu, s, o);
        if (threadIdx.x == 0) atomicAdd(out, s);
    }
}

// hcat[:,128:256] = b_gat[l]
__global__ void init_gat_k(float* __restrict__ hcat, const float* __restrict__ bgat, int n) {
    int idx = blockIdx.x * blockDim.x + threadIdx.x;
    if (idx < n * D) {
        int node = idx >> 7, d = idx & 127;
        hcat[(long)node * 256 + 128 + d] = bgat[d];
    }
}

__global__ void init_mh_k(float* __restrict__ m, float* __restrict__ den, int n) {
    int idx = blockIdx.x * blockDim.x + threadIdx.x;
    if (idx < n * NH) { m[idx] = -INFINITY; den[idx] = 0.0f; }
}

// warp per edge: hcat[dst, 0:128] += ht[src, etype, :]
__global__ void scatter_rel_k(const float* __restrict__ ht,
                              const int* __restrict__ src, const int* __restrict__ dst,
                              const int* __restrict__ et,
                              float* __restrict__ hcat, int E)
{
    int w = (blockIdx.x * blockDim.x + threadIdx.x) >> 5;
    if (w >= E) return;
    int lane = threadIdx.x & 31;
    int s = src[w], d = dst[w], r = et[w];
    int d0 = lane * 4;
    float4 v = *(const float4*)(ht + (long)s * 2048 + r * 128 + d0);
    red_add_v4(hcat + (long)d * 256 + d0, v.x, v.y, v.z, v.w);
}

// per (n,h): el/er = sum(z[n,h,:] * attn)
__global__ void eler_k(const float* __restrict__ z,
                       const float* __restrict__ al, const float* __restrict__ ar,
                       float* __restrict__ el, float* __restrict__ er, int n)
{
    int idx = blockIdx.x * blockDim.x + threadIdx.x;
    if (idx >= n * NH) return;
    int node = idx >> 2, h = idx & 3;
    const float* zr = z + (long)node * D + h * DH;
    const float* a = al + h * DH;
    const float* b = ar + h * DH;
    float sl = 0.0f, sr = 0.0f;
#pragma unroll
    for (int k = 0; k < DH; k++) {
        float zv = zr[k];
        sl = fmaf(zv, __ldg(a + k), sl);
        sr = fmaf(zv, __ldg(b + k), sr);
    }
    el[idx] = sl; er[idx] = sr;
}

__global__ void edge_max_k(const int* __restrict__ src, const int* __restrict__ dst,
                           const float* __restrict__ el, const float* __restrict__ er,
                           float* __restrict__ ebuf, float* __restrict__ m, int E)
{
    int idx = blockIdx.x * blockDim.x + threadIdx.x;
    if (idx >= E * NH) return;
    int e = idx >> 2, h = idx & 3;
    int s = src[e], d = dst[e];
    float v = el[s * NH + h] + er[d * NH + h];
    v = (v >= 0.0f) ? v : 0.2f * v;     // leaky_relu 0.2
    ebuf[idx] = v;
    atomicMaxF(&m[d * NH + h], v);
}

__global__ void edge_exp_k(const int* __restrict__ dst,
                           float* __restrict__ ebuf, const float* __restrict__ m,
                           float* __restrict__ den, int E)
{
    int idx = blockIdx.x * blockDim.x + threadIdx.x;
    if (idx >= E * NH) return;
    int e = idx >> 2, h = idx & 3;
    int d = dst[e];
    float ex = expf(ebuf[idx] - m[d * NH + h]);
    ebuf[idx] = ex;
    atomicAdd(&den[d * NH + h], ex);
}

// warp per edge: hcat[dst, 128:256] += alpha * z[src]
__global__ void gat_agg_k(const int* __restrict__ src, const int* __restrict__ dst,
                          const float* __restrict__ ebuf, const float* __restrict__ den,
                          const float* __restrict__ z, float* __restrict__ hcat, int E)
{
    int w = (blockIdx.x * blockDim.x + threadIdx.x) >> 5;
    if (w >= E) return;
    int lane = threadIdx.x & 31;
    int s = src[w], d = dst[w];
    int head = lane >> 3;               // (lane*4)/32
    int d0 = lane * 4;
    float alpha = ebuf[w * NH + head] / den[d * NH + head];
    float4 zv = *(const float4*)(z + (long)s * D + d0);
    red_add_v4(hcat + (long)d * 256 + 128 + d0,
               alpha * zv.x, alpha * zv.y, alpha * zv.z, alpha * zv.w);
}

// ---------------- launcher ---------------------------------------------------
extern "C" void kernel_launch(void* const* d_in, const int* in_sizes, int n_in,
                              void* d_out, int out_size)
{
    const float* feat   = (const float*)d_in[0];
    const int*   src    = (const int*)  d_in[1];
    const int*   dst    = (const int*)  d_in[2];
    const int*   et     = (const int*)  d_in[3];
    const float* tw     = (const float*)d_in[4];
    const float* W_rel  = (const float*)d_in[5];   // [L,R,D,D]
    const float* b_rel  = (const float*)d_in[6];   // [L,D]
    const float* W_loop = (const float*)d_in[7];   // [L,D,D]
    const float* W_gat  = (const float*)d_in[8];   // [L,D,D]
    const float* attn_l = (const float*)d_in[9];   // [L,H,DH]
    const float* attn_r = (const float*)d_in[10];  // [L,H,DH]
    const float* b_gat  = (const float*)d_in[11];  // [L,D]
    const float* W_fuse = (const float*)d_in[12];  // [2D,D]
    const float* b_fuse = (const float*)d_in[13];  // [D]
    const float* W_gate = (const float*)d_in[14];  // [D+1,D]
    const float* b_gate = (const float*)d_in[15];  // [D]

    const int Nn = in_sizes[0] / D;
    const int E  = in_sizes[1];

    float *ht, *hcat, *h, *z, *el, *er, *m, *den, *ebuf, *tws;
    cudaGetSymbolAddress((void**)&ht,   g_ht);
    cudaGetSymbolAddress((void**)&hcat, g_hcat);
    cudaGetSymbolAddress((void**)&h,    g_h);
    cudaGetSymbolAddress((void**)&z,    g_z);
    cudaGetSymbolAddress((void**)&el,   g_el);
    cudaGetSymbolAddress((void**)&er,   g_er);
    cudaGetSymbolAddress((void**)&m,    g_m);
    cudaGetSymbolAddress((void**)&den,  g_den);
    cudaGetSymbolAddress((void**)&ebuf, g_ebuf);
    cudaGetSymbolAddress((void**)&tws,  g_twsum);

    const int MB = (Nn + 127) / 128;
    const int TPB = 256;
    const int eh_blocks   = (E * NH + TPB - 1) / TPB;
    const int ewarp_blocks = (E * 32 + TPB - 1) / TPB;
    const int nd_blocks   = (Nn * D + TPB - 1) / TPB;
    const int nh_blocks   = (Nn * NH + TPB - 1) / TPB;

    // temporal_weight mean (used only in layer-0 gate)
    zero_scalar_k<<<1, 1>>>(tws);
    reduce_sum_k<<<256, 256>>>(tw, tws, E);

    const float* X = feat;
    for (int l = 0; l < NL; l++) {
        const float* Wrel_l  = W_rel  + (long)l * R * D * D;
        const float* Wloop_l = W_loop + (long)l * D * D;
        const float* Wgat_l  = W_gat  + (long)l * D * D;
        const float* brel_l  = b_rel  + l * D;
        const float* bgat_l  = b_gat  + l * D;
        const float* al_l    = attn_l + l * NH * DH;
        const float* ar_l    = attn_r + l * NH * DH;

        // 1) ht[:, r, :] = X @ W_rel[l, r]  for all 16 relations
        sgemm_k<0><<<dim3(MB, R), TPB>>>(X, D, Wrel_l, D, (long)D * D,
                                         ht, R * D, (long)D,
                                         Nn, D, nullptr, nullptr, nullptr, 0.f);
        // 2) hcat[:, 0:128] = X @ W_loop[l] + b_rel[l]
        sgemm_k<0><<<dim3(MB, 1), TPB>>>(X, D, Wloop_l, D, 0,
                                         hcat, 2 * D, 0,
                                         Nn, D, brel_l, nullptr, nullptr, 0.f);
        // 3) init hcat[:,128:256]=b_gat ; m=-inf ; den=0
        init_gat_k<<<nd_blocks, TPB>>>(hcat, bgat_l, Nn);
        init_mh_k<<<nh_blocks, TPB>>>(m, den, Nn);
        // 4) RelConv scatter
        scatter_rel_k<<<ewarp_blocks, TPB>>>(ht, src, dst, et, hcat, E);
        // 5) z = X @ W_gat[l]
        sgemm_k<0><<<dim3(MB, 1), TPB>>>(X, D, Wgat_l, D, 0,
                                         z, D, 0,
                                         Nn, D, nullptr, nullptr, nullptr, 0.f);
        // 6) el/er
        eler_k<<<nh_blocks, TPB>>>(z, al_l, ar_l, el, er, Nn);
        // 7) edge leaky-relu + segment max
        edge_max_k<<<eh_blocks, TPB>>>(src, dst, el, er, ebuf, m, E);
        // 8) exp + segment sum
        edge_exp_k<<<eh_blocks, TPB>>>(dst, ebuf, m, den, E);
        // 9) weighted aggregation into hcat[:,128:256]
        gat_agg_k<<<ewarp_blocks, TPB>>>(src, dst, ebuf, den, z, hcat, E);

        // 10) fuse (+ gate at layer 0), output into h (or d_out at last layer)
        float* out_l = (l == NL - 1) ? (float*)d_out : h;
        if (l == 0) {
            // hc (pre-gate) -> z buffer (z no longer needed)
            sgemm_k<0><<<dim3(MB, 1), TPB>>>(hcat, 2 * D, W_fuse, D, 0,
                                             z, D, 0,
                                             Nn, 2 * D, b_fuse, nullptr, nullptr, 0.f);
            // out = relu(hc * sigmoid(hc@W_gate[:D] + twm*W_gate[D] + b_gate))
            sgemm_k<3><<<dim3(MB, 1), TPB>>>(z, D, W_gate, D, 0,
                                             out_l, D, 0,
                                             Nn, D, b_gate, W_gate + (long)D * D,
                                             tws, 1.0f / (float)E);
        } else {
            sgemm_k<2><<<dim3(MB, 1), TPB>>>(hcat, 2 * D, W_fuse, D, 0,
                                             out_l, D, 0,
                                             Nn, 2 * D, b_fuse, nullptr, nullptr, 0.f);
        }
        X = h;
    }
}

// round 2
// speedup vs baseline: 1.4515x; 1.4515x over previous
#include <cuda_runtime.h>
#include <cuda_bf16.h>
#include <math.h>
#include <stdint.h>

// Problem constants (SubgraphGNN): N=30000, E=480000, D=128, R=16, H=4, DH=32, L=3
#define MAXN 30000
#define MAXE 480000
#define D 128
#define R 16
#define NH 4
#define DH 32
#define NL 3

// ---------------- scratch (static device globals; no cudaMalloc allowed) ----
__device__ float g_ht[(long)MAXN * (R * D)];      // [N, R*D]
__device__ float g_hcat[(long)MAXN * (2 * D)];    // [N, 256]
__device__ float g_h[(long)MAXN * D];
__device__ float g_z[(long)MAXN * D];
__device__ float g_el[MAXN * NH];
__device__ float g_er[MAXN * NH];
__device__ float g_m[MAXN * NH];
__device__ float g_den[MAXN * NH];
__device__ float g_ebuf[MAXE * NH];
__device__ float g_twsum;

// ---------------- helpers ---------------------------------------------------
__device__ __forceinline__ void red_add_v4(float* p, float x, float y, float z, float w) {
#if __CUDA_ARCH__ >= 900
    asm volatile("red.global.add.v4.f32 [%0], {%1, %2, %3, %4};"
                 :: "l"(p), "f"(x), "f"(y), "f"(z), "f"(w) : "memory");
#else
    atomicAdd(p + 0, x); atomicAdd(p + 1, y); atomicAdd(p + 2, z); atomicAdd(p + 3, w);
#endif
}

__device__ __forceinline__ void atomicMaxF(float* addr, float val) {
    if (val >= 0.0f) atomicMax((int*)addr, __float_as_int(val));
    else             atomicMin((unsigned int*)addr, (unsigned int)__float_as_int(val));
}

__device__ __forceinline__ uint32_t tf32_of(float x) {
    uint32_t u; asm("cvt.rna.tf32.f32 %0, %1;" : "=r"(u) : "f"(x)); return u;
}

__device__ __forceinline__ void ldsm4(uint32_t r[4], uint32_t addr) {
    asm volatile("ldmatrix.sync.aligned.m8n8.x4.shared.b16 {%0,%1,%2,%3}, [%4];"
                 : "=r"(r[0]), "=r"(r[1]), "=r"(r[2]), "=r"(r[3]) : "r"(addr));
}

__device__ __forceinline__ void mma8(float c[4], const uint32_t a[4], const uint32_t b[2]) {
    asm volatile("mma.sync.aligned.m16n8k8.row.col.f32.tf32.tf32.f32 "
                 "{%0,%1,%2,%3}, {%4,%5,%6,%7}, {%8,%9}, {%0,%1,%2,%3};"
                 : "+f"(c[0]), "+f"(c[1]), "+f"(c[2]), "+f"(c[3])
                 : "r"(a[0]), "r"(a[1]), "r"(a[2]), "r"(a[3]), "r"(b[0]), "r"(b[1]));
}

// ---------------- tf32x3 tensor-core GEMM -----------------------------------
// C[M,128] = A[M,K] @ B[K,128]  (fp32 in/out, tf32x3 emulation, fp32 accuracy)
// CTA tile 128x128, BK=32, 512 threads (16 warps as 4(m) x 4(n), warp tile 32x32)
// EPI: 0 = none(+opt bias), 2 = bias+relu, 3 = temporal gate (layer-0 only)
#define AS_LD 36     // A smem row stride (floats): conflict-free LDSM (9r+c mod 8 distinct)
#define BS_LD 136    // B smem row stride (floats): banks 8*tig+grp all-distinct
#define SMEM_BYTES ((128 * AS_LD * 2 + 32 * BS_LD * 2) * 4)   // 71680 B

template <int EPI>
__global__ __launch_bounds__(512)
void tc_gemm(const float* __restrict__ A, int lda,
             const float* __restrict__ Bg, int ldb, long bstr,
             float* __restrict__ Cg, int ldc, long cstr,
             int M, int K,
             const float* __restrict__ bias,
             const float* __restrict__ gate_wlast,
             const float* __restrict__ tw_sum, float invE)
{
    extern __shared__ float sm[];
    float* Ahi = sm;
    float* Alo = Ahi + 128 * AS_LD;
    float* Bhi = Alo + 128 * AS_LD;
    float* Blo = Bhi + 32 * BS_LD;

    const float* B = Bg + (long)blockIdx.y * bstr;
    float*       C = Cg + (long)blockIdx.y * cstr;
    const int m0   = blockIdx.x * 128;
    const int tid  = threadIdx.x;
    const int lane = tid & 31;
    const int wid  = tid >> 5;
    const int grp  = lane >> 2;
    const int tig  = lane & 3;
    const int wm   = (wid >> 2) * 32;
    const int wn   = (wid & 3) * 32;

    float4 pa[2], pb[2];

    auto ldg_chunk = [&](int k0) {
#pragma unroll
        for (int i = 0; i < 2; i++) {
            int v = tid + i * 512;
            int arow = v >> 3, ak = (v & 7) * 4;
            int gm = m0 + arow;
            pa[i] = (gm < M) ? *(const float4*)(A + (long)gm * lda + k0 + ak)
                             : make_float4(0.f, 0.f, 0.f, 0.f);
            int bk = v >> 5, bn = (v & 31) * 4;
            pb[i] = *(const float4*)(B + (long)(k0 + bk) * ldb + bn);
        }
    };
    auto sts_chunk = [&]() {
#pragma unroll
        for (int i = 0; i < 2; i++) {
            int v = tid + i * 512;
            int arow = v >> 3, ak = (v & 7) * 4;
            float4 a = pa[i];
            float4 h, l;
            h.x = __uint_as_float(tf32_of(a.x)); l.x = __uint_as_float(tf32_of(a.x - h.x));
            h.y = __uint_as_float(tf32_of(a.y)); l.y = __uint_as_float(tf32_of(a.y - h.y));
            h.z = __uint_as_float(tf32_of(a.z)); l.z = __uint_as_float(tf32_of(a.z - h.z));
            h.w = __uint_as_float(tf32_of(a.w)); l.w = __uint_as_float(tf32_of(a.w - h.w));
            *(float4*)(Ahi + arow * AS_LD + ak) = h;
            *(float4*)(Alo + arow * AS_LD + ak) = l;

            int bk = v >> 5, bn = (v & 31) * 4;
            float4 b = pb[i];
            h.x = __uint_as_float(tf32_of(b.x)); l.x = __uint_as_float(tf32_of(b.x - h.x));
            h.y = __uint_as_float(tf32_of(b.y)); l.y = __uint_as_float(tf32_of(b.y - h.y));
            h.z = __uint_as_float(tf32_of(b.z)); l.z = __uint_as_float(tf32_of(b.z - h.z));
            h.w = __uint_as_float(tf32_of(b.w)); l.w = __uint_as_float(tf32_of(b.w - h.w));
            *(float4*)(Bhi + bk * BS_LD + bn) = h;
            *(float4*)(Blo + bk * BS_LD + bn) = l;
        }
    };

    float acc[2][4][4];
#pragma unroll
    for (int i = 0; i < 2; i++)
#pragma unroll
        for (int j = 0; j < 4; j++)
#pragma unroll
            for (int k = 0; k < 4; k++) acc[i][j][k] = 0.f;

    // per-thread ldmatrix base: row = wm + mt*16 + (lane&15), kcol = ks*8 + (lane>>4)*4
    const int arow_l  = wm + (lane & 15);
    const int akoff_l = (lane >> 4) * 4;
    const uint32_t aHiBase = (uint32_t)__cvta_generic_to_shared(Ahi) + ((arow_l * AS_LD + akoff_l) << 2);
    const uint32_t aLoBase = (uint32_t)__cvta_generic_to_shared(Alo) + ((arow_l * AS_LD + akoff_l) << 2);

    const int nch = K >> 5;
    ldg_chunk(0);
    sts_chunk();
    __syncthreads();

    for (int c = 0; c < nch; c++) {
        if (c + 1 < nch) ldg_chunk((c + 1) << 5);
#pragma unroll
        for (int ks = 0; ks < 4; ks++) {
            uint32_t ah[2][4], al[2][4], bh[4][2], bl[4][2];
#pragma unroll
            for (int mt = 0; mt < 2; mt++) {
                ldsm4(ah[mt], aHiBase + (((mt * 16) * AS_LD + ks * 8) << 2));
                ldsm4(al[mt], aLoBase + (((mt * 16) * AS_LD + ks * 8) << 2));
            }
#pragma unroll
            for (int nt = 0; nt < 4; nt++) {
                int n = wn + nt * 8 + grp;
                bh[nt][0] = __float_as_uint(Bhi[(ks * 8 + tig) * BS_LD + n]);
                bh[nt][1] = __float_as_uint(Bhi[(ks * 8 + tig + 4) * BS_LD + n]);
                bl[nt][0] = __float_as_uint(Blo[(ks * 8 + tig) * BS_LD + n]);
                bl[nt][1] = __float_as_uint(Blo[(ks * 8 + tig + 4) * BS_LD + n]);
            }
#pragma unroll
            for (int mt = 0; mt < 2; mt++)
#pragma unroll
                for (int nt = 0; nt < 4; nt++) {
                    mma8(acc[mt][nt], ah[mt], bh[nt]);
                    mma8(acc[mt][nt], al[mt], bh[nt]);
                    mma8(acc[mt][nt], ah[mt], bl[nt]);
                }
        }
        __syncthreads();
        if (c + 1 < nch) { sts_chunk(); __syncthreads(); }
    }

    // ---------------- epilogue ----------------
    float twm = 0.0f;
    if (EPI == 3) twm = tw_sum[0] * invE;

#pragma unroll
    for (int mt = 0; mt < 2; mt++)
#pragma unroll
        for (int nt = 0; nt < 4; nt++) {
            const int n = wn + nt * 8 + 2 * tig;
#pragma unroll
            for (int half = 0; half < 2; half++) {
                const int gm = m0 + wm + mt * 16 + grp + half * 8;
                if (gm >= M) continue;
                float v0 = acc[mt][nt][half * 2 + 0];
                float v1 = acc[mt][nt][half * 2 + 1];
                if (bias) { v0 += bias[n]; v1 += bias[n + 1]; }
                if (EPI == 2) { v0 = fmaxf(v0, 0.f); v1 = fmaxf(v1, 0.f); }
                if (EPI == 3) {
                    float g0 = v0 + twm * gate_wlast[n];
                    float g1 = v1 + twm * gate_wlast[n + 1];
                    g0 = 1.0f / (1.0f + expf(-g0));
                    g1 = 1.0f / (1.0f + expf(-g1));
                    float2 hc = *(const float2*)(A + (long)gm * lda + n);
                    v0 = fmaxf(hc.x * g0, 0.f);
                    v1 = fmaxf(hc.y * g1, 0.f);
                }
                float2 o; o.x = v0; o.y = v1;
                *(float2*)(C + (long)gm * ldc + n) = o;
            }
        }
}

// ---------------- small kernels ---------------------------------------------
__global__ void zero_scalar_k(float* p) { *p = 0.0f; }

__global__ void reduce_sum_k(const float* __restrict__ x, float* out, int n) {
    float s = 0.0f;
    for (int i = blockIdx.x * blockDim.x + threadIdx.x; i < n; i += gridDim.x * blockDim.x)
        s += x[i];
#pragma unroll
    for (int o = 16; o > 0; o >>= 1) s += __shfl_xor_sync(0xFFFFFFFFu, s, o);
    __shared__ float ws[8];
    if ((threadIdx.x & 31) == 0) ws[threadIdx.x >> 5] = s;
    __syncthreads();
    if (threadIdx.x < 32) {
        s = (threadIdx.x < (blockDim.x >> 5)) ? ws[threadIdx.x] : 0.0f;
#pragma unroll
        for (int o = 4; o > 0; o >>= 1) s += __shfl_xor_sync(0xFFFFFFFFu, s, o);
        if (threadIdx.x == 0) atomicAdd(out, s);
    }
}

__global__ void init_gat_k(float* __restrict__ hcat, const float* __restrict__ bgat, int n) {
    int idx = blockIdx.x * blockDim.x + threadIdx.x;
    if (idx < n * D) {
        int node = idx >> 7, d = idx & 127;
        hcat[(long)node * 256 + 128 + d] = bgat[d];
    }
}

__global__ void init_mh_k(float* __restrict__ m, float* __restrict__ den, int n) {
    int idx = blockIdx.x * blockDim.x + threadIdx.x;
    if (idx < n * NH) { m[idx] = -INFINITY; den[idx] = 0.0f; }
}

__global__ void scatter_rel_k(const float* __restrict__ ht,
                              const int* __restrict__ src, const int* __restrict__ dst,
                              const int* __restrict__ et,
                              float* __restrict__ hcat, int E)
{
    int w = (blockIdx.x * blockDim.x + threadIdx.x) >> 5;
    if (w >= E) return;
    int lane = threadIdx.x & 31;
    int s = src[w], d = dst[w], r = et[w];
    int d0 = lane * 4;
    float4 v = *(const float4*)(ht + (long)s * 2048 + r * 128 + d0);
    red_add_v4(hcat + (long)d * 256 + d0, v.x, v.y, v.z, v.w);
}

__global__ void eler_k(const float* __restrict__ z,
                       const float* __restrict__ al, const float* __restrict__ ar,
                       float* __restrict__ el, float* __restrict__ er, int n)
{
    int idx = blockIdx.x * blockDim.x + threadIdx.x;
    if (idx >= n * NH) return;
    int node = idx >> 2, h = idx & 3;
    const float* zr = z + (long)node * D + h * DH;
    const float* a = al + h * DH;
    const float* b = ar + h * DH;
    float sl = 0.0f, sr = 0.0f;
#pragma unroll
    for (int k = 0; k < DH; k++) {
        float zv = zr[k];
        sl = fmaf(zv, __ldg(a + k), sl);
        sr = fmaf(zv, __ldg(b + k), sr);
    }
    el[idx] = sl; er[idx] = sr;
}

__global__ void edge_max_k(const int* __restrict__ src, const int* __restrict__ dst,
                           const float* __restrict__ el, const float* __restrict__ er,
                           float* __restrict__ ebuf, float* __restrict__ m, int E)
{
    int idx = blockIdx.x * blockDim.x + threadIdx.x;
    if (idx >= E * NH) return;
    int e = idx >> 2, h = idx & 3;
    int s = src[e], d = dst[e];
    float v = el[s * NH + h] + er[d * NH + h];
    v = (v >= 0.0f) ? v : 0.2f * v;
    ebuf[idx] = v;
    atomicMaxF(&m[d * NH + h], v);
}

__global__ void edge_exp_k(const int* __restrict__ dst,
                           float* __restrict__ ebuf, const float* __restrict__ m,
                           float* __restrict__ den, int E)
{
    int idx = blockIdx.x * blockDim.x + threadIdx.x;
    if (idx >= E * NH) return;
    int e = idx >> 2, h = idx & 3;
    int d = dst[e];
    float ex = expf(ebuf[idx] - m[d * NH + h]);
    ebuf[idx] = ex;
    atomicAdd(&den[d * NH + h], ex);
}

__global__ void gat_agg_k(const int* __restrict__ src, const int* __restrict__ dst,
                          const float* __restrict__ ebuf, const float* __restrict__ den,
                          const float* __restrict__ z, float* __restrict__ hcat, int E)
{
    int w = (blockIdx.x * blockDim.x + threadIdx.x) >> 5;
    if (w >= E) return;
    int lane = threadIdx.x & 31;
    int s = src[w], d = dst[w];
    int head = lane >> 3;
    int d0 = lane * 4;
    float alpha = ebuf[w * NH + head] / den[d * NH + head];
    float4 zv = *(const float4*)(z + (long)s * D + d0);
    red_add_v4(hcat + (long)d * 256 + 128 + d0,
               alpha * zv.x, alpha * zv.y, alpha * zv.z, alpha * zv.w);
}

// ---------------- launcher ---------------------------------------------------
extern "C" void kernel_launch(void* const* d_in, const int* in_sizes, int n_in,
                              void* d_out, int out_size)
{
    const float* feat   = (const float*)d_in[0];
    const int*   src    = (const int*)  d_in[1];
    const int*   dst    = (const int*)  d_in[2];
    const int*   et     = (const int*)  d_in[3];
    const float* tw     = (const float*)d_in[4];
    const float* W_rel  = (const float*)d_in[5];
    const float* b_rel  = (const float*)d_in[6];
    const float* W_loop = (const float*)d_in[7];
    const float* W_gat  = (const float*)d_in[8];
    const float* attn_l = (const float*)d_in[9];
    const float* attn_r = (const float*)d_in[10];
    const float* b_gat  = (const float*)d_in[11];
    const float* W_fuse = (const float*)d_in[12];
    const float* b_fuse = (const float*)d_in[13];
    const float* W_gate = (const float*)d_in[14];
    const float* b_gate = (const float*)d_in[15];

    const int Nn = in_sizes[0] / D;
    const int E  = in_sizes[1];

    // allow 70KB dynamic smem (idempotent; set before first launch of each inst.)
    cudaFuncSetAttribute(tc_gemm<0>, cudaFuncAttributeMaxDynamicSharedMemorySize, SMEM_BYTES);
    cudaFuncSetAttribute(tc_gemm<2>, cudaFuncAttributeMaxDynamicSharedMemorySize, SMEM_BYTES);
    cudaFuncSetAttribute(tc_gemm<3>, cudaFuncAttributeMaxDynamicSharedMemorySize, SMEM_BYTES);

    float *ht, *hcat, *h, *z, *el, *er, *m, *den, *ebuf, *tws;
    cudaGetSymbolAddress((void**)&ht,   g_ht);
    cudaGetSymbolAddress((void**)&hcat, g_hcat);
    cudaGetSymbolAddress((void**)&h,    g_h);
    cudaGetSymbolAddress((void**)&z,    g_z);
    cudaGetSymbolAddress((void**)&el,   g_el);
    cudaGetSymbolAddress((void**)&er,   g_er);
    cudaGetSymbolAddress((void**)&m,    g_m);
    cudaGetSymbolAddress((void**)&den,  g_den);
    cudaGetSymbolAddress((void**)&ebuf, g_ebuf);
    cudaGetSymbolAddress((void**)&tws,  g_twsum);

    const int MB = (Nn + 127) / 128;
    const int TPB = 256;
    const int eh_blocks    = (E * NH + TPB - 1) / TPB;
    const int ewarp_blocks = (E * 32 + TPB - 1) / TPB;
    const int nd_blocks    = (Nn * D + TPB - 1) / TPB;
    const int nh_blocks    = (Nn * NH + TPB - 1) / TPB;

    zero_scalar_k<<<1, 1>>>(tws);
    reduce_sum_k<<<256, 256>>>(tw, tws, E);

    const float* X = feat;
    for (int l = 0; l < NL; l++) {
        const float* Wrel_l  = W_rel  + (long)l * R * D * D;
        const float* Wloop_l = W_loop + (long)l * D * D;
        const float* Wgat_l  = W_gat  + (long)l * D * D;
        const float* brel_l  = b_rel  + l * D;
        const float* bgat_l  = b_gat  + l * D;
        const float* al_l    = attn_l + l * NH * DH;
        const float* ar_l    = attn_r + l * NH * DH;

        // 1) ht[:, r, :] = X @ W_rel[l, r]
        tc_gemm<0><<<dim3(MB, R), 512, SMEM_BYTES>>>(X, D, Wrel_l, D, (long)D * D,
                                                     ht, R * D, (long)D,
                                                     Nn, D, nullptr, nullptr, nullptr, 0.f);
        // 2) hcat[:, 0:128] = X @ W_loop[l] + b_rel[l]
        tc_gemm<0><<<dim3(MB, 1), 512, SMEM_BYTES>>>(X, D, Wloop_l, D, 0,
                                                     hcat, 2 * D, 0,
                                                     Nn, D, brel_l, nullptr, nullptr, 0.f);
        // 3) init
        init_gat_k<<<nd_blocks, TPB>>>(hcat, bgat_l, Nn);
        init_mh_k<<<nh_blocks, TPB>>>(m, den, Nn);
        // 4) RelConv scatter
        scatter_rel_k<<<ewarp_blocks, TPB>>>(ht, src, dst, et, hcat, E);
        // 5) z = X @ W_gat[l]
        tc_gemm<0><<<dim3(MB, 1), 512, SMEM_BYTES>>>(X, D, Wgat_l, D, 0,
                                                     z, D, 0,
                                                     Nn, D, nullptr, nullptr, nullptr, 0.f);
        // 6-9) GAT edge softmax + aggregation
        eler_k<<<nh_blocks, TPB>>>(z, al_l, ar_l, el, er, Nn);
        edge_max_k<<<eh_blocks, TPB>>>(src, dst, el, er, ebuf, m, E);
        edge_exp_k<<<eh_blocks, TPB>>>(dst, ebuf, m, den, E);
        gat_agg_k<<<ewarp_blocks, TPB>>>(src, dst, ebuf, den, z, hcat, E);

        // 10) fuse (+ gate at layer 0)
        float* out_l = (l == NL - 1) ? (float*)d_out : h;
        if (l == 0) {
            tc_gemm<0><<<dim3(MB, 1), 512, SMEM_BYTES>>>(hcat, 2 * D, W_fuse, D, 0,
                                                         z, D, 0,
                                                         Nn, 2 * D, b_fuse, nullptr, nullptr, 0.f);
            tc_gemm<3><<<dim3(MB, 1), 512, SMEM_BYTES>>>(z, D, W_gate, D, 0,
                                                         out_l, D, 0,
                                                         Nn, D, b_gate, W_gate + (long)D * D,
                                                         tws, 1.0f / (float)E);
        } else {
            tc_gemm<2><<<dim3(MB, 1), 512, SMEM_BYTES>>>(hcat, 2 * D, W_fuse, D, 0,
                                                         out_l, D, 0,
                                                         Nn, 2 * D, b_fuse, nullptr, nullptr, 0.f);
        }
        X = h;
    }
}

// round 3
// speedup vs baseline: 1.9802x; 1.3642x over previous
#include <cuda_runtime.h>
#include <cuda_bf16.h>
#include <math.h>
#include <stdint.h>

// Problem constants: N=30000, E=480000, D=128, R=16, H=4, DH=32, L=3
#define MAXN 30000
#define MAXE 480000
#define D 128
#define R 16
#define NH 4
#define DH 32
#define NL 3

// ---------------- scratch ----------------------------------------------------
__device__ float g_ht[(long)MAXN * (R * D)];
__device__ float g_hcat[(long)MAXN * (2 * D)];
__device__ float g_h[(long)MAXN * D];
__device__ float g_z[(long)MAXN * D];
__device__ float g_el[MAXN * NH];
__device__ float g_er[MAXN * NH];
__device__ float g_m[MAXN * NH];
__device__ float g_den[MAXN * NH];
__device__ float g_ebuf[MAXE * NH];
__device__ float g_twsum;
// bf16 hi/lo activation buffers (max K = 256)
__device__ __nv_bfloat16 g_xhi[(long)MAXN * 256];
__device__ __nv_bfloat16 g_xlo[(long)MAXN * 256];
// packed bf16-pair weights: rows of 128 words; layout:
//   [0,1024): W_rel[l] (16 x 64)  [1024,1088): W_loop  [1088,1152): W_gat
//   [1152,1280): W_fuse (K=256)   [1280,1344): W_gate (first 128 rows)
#define WPK_ROWS 1344
__device__ uint32_t g_wpk_hi[WPK_ROWS * 128];
__device__ uint32_t g_wpk_lo[WPK_ROWS * 128];

// ---------------- helpers ----------------------------------------------------
__device__ __forceinline__ void red_add_v4(float* p, float x, float y, float z, float w) {
    asm volatile("red.global.add.v4.f32 [%0], {%1, %2, %3, %4};"
                 :: "l"(p), "f"(x), "f"(y), "f"(z), "f"(w) : "memory");
}
__device__ __forceinline__ void atomicMaxF(float* addr, float val) {
    if (val >= 0.0f) atomicMax((int*)addr, __float_as_int(val));
    else             atomicMin((unsigned int*)addr, (unsigned int)__float_as_int(val));
}
__device__ __forceinline__ void ldsm4(uint32_t r[4], uint32_t addr) {
    asm volatile("ldmatrix.sync.aligned.m8n8.x4.shared.b16 {%0,%1,%2,%3}, [%4];"
                 : "=r"(r[0]), "=r"(r[1]), "=r"(r[2]), "=r"(r[3]) : "r"(addr));
}
__device__ __forceinline__ void mma16816(float c[4], const uint32_t a[4], const uint32_t b[2]) {
    asm volatile("mma.sync.aligned.m16n8k16.row.col.f32.bf16.bf16.f32 "
                 "{%0,%1,%2,%3}, {%4,%5,%6,%7}, {%8,%9}, {%0,%1,%2,%3};"
                 : "+f"(c[0]), "+f"(c[1]), "+f"(c[2]), "+f"(c[3])
                 : "r"(a[0]), "r"(a[1]), "r"(a[2]), "r"(a[3]), "r"(b[0]), "r"(b[1]));
}
__device__ __forceinline__ void cp16(uint32_t dst, const void* src, bool pred) {
    int sz = pred ? 16 : 0;
    asm volatile("cp.async.cg.shared.global [%0], [%1], 16, %2;"
                 :: "r"(dst), "l"(src), "r"(sz));
}
__device__ __forceinline__ void cp_commit() { asm volatile("cp.async.commit_group;"); }
template <int NN> __device__ __forceinline__ void cp_wait() {
    asm volatile("cp.async.wait_group %0;" :: "n"(NN));
}

// ---------------- conversion kernels ------------------------------------------
// fp32 [M*K] -> bf16 hi/lo
__global__ void cvt_act_k(const float* __restrict__ x,
                          __nv_bfloat16* __restrict__ hi, __nv_bfloat16* __restrict__ lo,
                          int total4)
{
    int i = blockIdx.x * blockDim.x + threadIdx.x;
    if (i >= total4) return;
    float4 v = ((const float4*)x)[i];
    __nv_bfloat16 h0 = __float2bfloat16_rn(v.x), h1 = __float2bfloat16_rn(v.y);
    __nv_bfloat16 h2 = __float2bfloat16_rn(v.z), h3 = __float2bfloat16_rn(v.w);
    __nv_bfloat162 H0; H0.x = h0; H0.y = h1;
    __nv_bfloat162 H1; H1.x = h2; H1.y = h3;
    ((__nv_bfloat162*)hi)[i * 2 + 0] = H0;
    ((__nv_bfloat162*)hi)[i * 2 + 1] = H1;
    __nv_bfloat162 L0, L1;
    L0.x = __float2bfloat16_rn(v.x - __bfloat162float(h0));
    L0.y = __float2bfloat16_rn(v.y - __bfloat162float(h1));
    L1.x = __float2bfloat16_rn(v.z - __bfloat162float(h2));
    L1.y = __float2bfloat16_rn(v.w - __bfloat162float(h3));
    ((__nv_bfloat162*)lo)[i * 2 + 0] = L0;
    ((__nv_bfloat162*)lo)[i * 2 + 1] = L1;
}

// W fp32 [K,128] row-major -> packed words [K/2][128]; word(k2,n) = (bf16(W[2k2][n]), bf16(W[2k2+1][n]))
__global__ void cvt_wt_k(const float* __restrict__ W,
                         uint32_t* __restrict__ hi, uint32_t* __restrict__ lo, int k2max)
{
    int i = blockIdx.x * blockDim.x + threadIdx.x;
    if (i >= k2max * 128) return;
    int k2 = i >> 7, n = i & 127;
    float a = W[(2 * k2) * 128 + n];
    float b = W[(2 * k2 + 1) * 128 + n];
    __nv_bfloat16 ah = __float2bfloat16_rn(a), bh = __float2bfloat16_rn(b);
    __nv_bfloat162 H; H.x = ah; H.y = bh;
    __nv_bfloat162 Lw;
    Lw.x = __float2bfloat16_rn(a - __bfloat162float(ah));
    Lw.y = __float2bfloat16_rn(b - __bfloat162float(bh));
    hi[i] = *(uint32_t*)&H;
    lo[i] = *(uint32_t*)&Lw;
}

// ---------------- bf16x3 tensor-core GEMM -------------------------------------
// C[M,128] = A[M,K] @ B[K,128]; A given as bf16 hi/lo [M,K]; B packed hi/lo words.
// CTA 128x128, BK=32, 512 threads (16 warps 4x4, warp tile 32x32), cp.async dbuf.
// EPI: 0 none(+bias), 2 bias+relu, 3 temporal gate. DUAL: blockIdx.y==1 -> C2 set.
#define AS_BUF 8192            // 128 rows * 64B
#define BS_BUF 8704            // 16 rows * 136 words * 4B
#define OFF_AHI 0
#define OFF_ALO (2 * AS_BUF)
#define OFF_BHI (4 * AS_BUF)
#define OFF_BLO (4 * AS_BUF + 2 * BS_BUF)
#define SMEM_BYTES (4 * AS_BUF + 4 * BS_BUF)   // 67584

template <int EPI, bool DUAL>
__global__ __launch_bounds__(512)
void bf_gemm(const __nv_bfloat16* __restrict__ Ahi, const __nv_bfloat16* __restrict__ Alo,
             int lda,
             const uint32_t* __restrict__ Bhi, const uint32_t* __restrict__ Blo, long bstr,
             float* __restrict__ C, int ldc, long cstr,
             float* __restrict__ C2, int ldc2,
             int M, int K,
             const float* __restrict__ bias, const float* __restrict__ bias2,
             const float* __restrict__ hcsrc,
             const float* __restrict__ gate_wlast,
             const float* __restrict__ tw_sum, float invE)
{
    extern __shared__ char sm[];
    const uint32_t smB = (uint32_t)__cvta_generic_to_shared(sm);

    const uint32_t* BhY = Bhi + (long)blockIdx.y * bstr;
    const uint32_t* BlY = Blo + (long)blockIdx.y * bstr;
    float* Cp; int ldcv; const float* biasv;
    if (DUAL && blockIdx.y == 1) { Cp = C2; ldcv = ldc2; biasv = bias2; }
    else { Cp = C + (long)blockIdx.y * cstr; ldcv = ldc; biasv = bias; }

    const int m0   = blockIdx.x * 128;
    const int tid  = threadIdx.x;
    const int lane = tid & 31;
    const int wid  = tid >> 5;
    const int grp  = lane >> 2;
    const int tig  = lane & 3;
    const int wm   = (wid >> 2) * 32;
    const int wn   = (wid & 3) * 32;

    // cp.async A: thread -> row=tid>>2 (0..127), chunk c16=tid&3; swizzled chunk
    const int aRow = tid >> 2;
    const int aC   = tid & 3;
    const int aSC  = aC ^ ((aRow >> 1) & 3);
    const int gmA  = m0 + aRow;
    const bool aOk = gmA < M;
    const long aSrcOff = (long)(aOk ? gmA : 0) * lda + aC * 8;
    const uint32_t aDst = aRow * 64 + aSC * 16;
    // cp.async B: row=tid>>5 (0..15), c=tid&31
    const int bRow = tid >> 5;
    const int bC   = tid & 31;
    const uint32_t bDst = bRow * 544 + bC * 16;
    const int bSrcOff = bRow * 128 + bC * 4;

    auto issue = [&](int k0, int b) {
        cp16(smB + OFF_AHI + b * AS_BUF + aDst, Ahi + aSrcOff + k0, aOk);
        cp16(smB + OFF_ALO + b * AS_BUF + aDst, Alo + aSrcOff + k0, aOk);
        cp16(smB + OFF_BHI + b * BS_BUF + bDst, BhY + (k0 >> 1) * 128 + bSrcOff, true);
        cp16(smB + OFF_BLO + b * BS_BUF + bDst, BlY + (k0 >> 1) * 128 + bSrcOff, true);
        cp_commit();
    };

    float acc[2][4][4];
#pragma unroll
    for (int i = 0; i < 2; i++)
#pragma unroll
        for (int j = 0; j < 4; j++)
#pragma unroll
            for (int k = 0; k < 4; k++) acc[i][j][k] = 0.f;

    // ldmatrix per-lane addressing
    const int arow_l  = wm + (lane & 15);
    const int aShift  = (arow_l >> 1) & 3;
    const int aChunk0 = lane >> 4;              // 0 or 1
    const uint32_t aRowByte = arow_l * 64;

    const int nch = K >> 5;
    issue(0, 0);

    for (int c = 0; c < nch; c++) {
        const int b = c & 1;
        if (c + 1 < nch) issue((c + 1) << 5, b ^ 1);
        if (c + 1 < nch) cp_wait<1>(); else cp_wait<0>();
        __syncthreads();

        const uint32_t* bsHi = (const uint32_t*)(sm + OFF_BHI + b * BS_BUF);
        const uint32_t* bsLo = (const uint32_t*)(sm + OFF_BLO + b * BS_BUF);
#pragma unroll
        for (int kc = 0; kc < 2; kc++) {
            uint32_t ah[2][4], al[2][4], bh[4][2], bl[4][2];
#pragma unroll
            for (int mt = 0; mt < 2; mt++) {
                const int sc = ((kc * 2 + aChunk0) ^ aShift) * 16;
                uint32_t off = aRowByte + mt * 1024 + sc;
                ldsm4(ah[mt], smB + OFF_AHI + b * AS_BUF + off);
                ldsm4(al[mt], smB + OFF_ALO + b * AS_BUF + off);
            }
#pragma unroll
            for (int nt = 0; nt < 4; nt++) {
                const int n = wn + nt * 8 + grp;
                bh[nt][0] = bsHi[(kc * 8 + tig) * 136 + n];
                bh[nt][1] = bsHi[(kc * 8 + tig + 4) * 136 + n];
                bl[nt][0] = bsLo[(kc * 8 + tig) * 136 + n];
                bl[nt][1] = bsLo[(kc * 8 + tig + 4) * 136 + n];
            }
#pragma unroll
            for (int mt = 0; mt < 2; mt++)
#pragma unroll
                for (int nt = 0; nt < 4; nt++) {
                    mma16816(acc[mt][nt], ah[mt], bh[nt]);
                    mma16816(acc[mt][nt], al[mt], bh[nt]);
                    mma16816(acc[mt][nt], ah[mt], bl[nt]);
                }
        }
        __syncthreads();
    }

    // ---------------- epilogue ----------------
    float twm = 0.0f;
    if (EPI == 3) twm = tw_sum[0] * invE;

#pragma unroll
    for (int mt = 0; mt < 2; mt++)
#pragma unroll
        for (int nt = 0; nt < 4; nt++) {
            const int n = wn + nt * 8 + 2 * tig;
#pragma unroll
            for (int half = 0; half < 2; half++) {
                const int gm = m0 + wm + mt * 16 + grp + half * 8;
                if (gm >= M) continue;
                float v0 = acc[mt][nt][half * 2 + 0];
                float v1 = acc[mt][nt][half * 2 + 1];
                if (biasv) { v0 += biasv[n]; v1 += biasv[n + 1]; }
                if (EPI == 2) { v0 = fmaxf(v0, 0.f); v1 = fmaxf(v1, 0.f); }
                if (EPI == 3) {
                    float g0 = v0 + twm * gate_wlast[n];
                    float g1 = v1 + twm * gate_wlast[n + 1];
                    g0 = 1.0f / (1.0f + expf(-g0));
                    g1 = 1.0f / (1.0f + expf(-g1));
                    float2 hc = *(const float2*)(hcsrc + (long)gm * 128 + n);
                    v0 = fmaxf(hc.x * g0, 0.f);
                    v1 = fmaxf(hc.y * g1, 0.f);
                }
                float2 o; o.x = v0; o.y = v1;
                *(float2*)(Cp + (long)gm * ldcv + n) = o;
            }
        }
}

// ---------------- small kernels ------------------------------------------------
__global__ void zero_scalar_k(float* p) { *p = 0.0f; }

__global__ void reduce_sum_k(const float* __restrict__ x, float* out, int n) {
    float s = 0.0f;
    for (int i = blockIdx.x * blockDim.x + threadIdx.x; i < n; i += gridDim.x * blockDim.x)
        s += x[i];
#pragma unroll
    for (int o = 16; o > 0; o >>= 1) s += __shfl_xor_sync(0xFFFFFFFFu, s, o);
    __shared__ float ws[8];
    if ((threadIdx.x & 31) == 0) ws[threadIdx.x >> 5] = s;
    __syncthreads();
    if (threadIdx.x < 32) {
        s = (threadIdx.x < (blockDim.x >> 5)) ? ws[threadIdx.x] : 0.0f;
#pragma unroll
        for (int o = 4; o > 0; o >>= 1) s += __shfl_xor_sync(0xFFFFFFFFu, s, o);
        if (threadIdx.x == 0) atomicAdd(out, s);
    }
}

__global__ void init_gat_k(float* __restrict__ hcat, const float* __restrict__ bgat, int n) {
    int idx = blockIdx.x * blockDim.x + threadIdx.x;
    if (idx < n * D) {
        int node = idx >> 7, d = idx & 127;
        hcat[(long)node * 256 + 128 + d] = bgat[d];
    }
}

__global__ void init_mh_k(float* __restrict__ m, float* __restrict__ den, int n) {
    int idx = blockIdx.x * blockDim.x + threadIdx.x;
    if (idx < n * NH) { m[idx] = -INFINITY; den[idx] = 0.0f; }
}

__global__ void scatter_rel_k(const float* __restrict__ ht,
                              const int* __restrict__ src, const int* __restrict__ dst,
                              const int* __restrict__ et,
                              float* __restrict__ hcat, int E)
{
    int w = (blockIdx.x * blockDim.x + threadIdx.x) >> 5;
    if (w >= E) return;
    int lane = threadIdx.x & 31;
    int s = src[w], d = dst[w], r = et[w];
    int d0 = lane * 4;
    float4 v = *(const float4*)(ht + (long)s * 2048 + r * 128 + d0);
    red_add_v4(hcat + (long)d * 256 + d0, v.x, v.y, v.z, v.w);
}

__global__ void eler_k(const float* __restrict__ z,
                       const float* __restrict__ al, const float* __restrict__ ar,
                       float* __restrict__ el, float* __restrict__ er, int n)
{
    int idx = blockIdx.x * blockDim.x + threadIdx.x;
    if (idx >= n * NH) return;
    int node = idx >> 2, h = idx & 3;
    const float* zr = z + (long)node * D + h * DH;
    const float* a = al + h * DH;
    const float* b = ar + h * DH;
    float sl = 0.0f, sr = 0.0f;
#pragma unroll
    for (int k = 0; k < DH; k++) {
        float zv = zr[k];
        sl = fmaf(zv, __ldg(a + k), sl);
        sr = fmaf(zv, __ldg(b + k), sr);
    }
    el[idx] = sl; er[idx] = sr;
}

__global__ void edge_max_k(const int* __restrict__ src, const int* __restrict__ dst,
                           const float* __restrict__ el, const float* __restrict__ er,
                           float* __restrict__ ebuf, float* __restrict__ m, int E)
{
    int idx = blockIdx.x * blockDim.x + threadIdx.x;
    if (idx >= E * NH) return;
    int e = idx >> 2, h = idx & 3;
    int s = src[e], d = dst[e];
    float v = el[s * NH + h] + er[d * NH + h];
    v = (v >= 0.0f) ? v : 0.2f * v;
    ebuf[idx] = v;
    atomicMaxF(&m[d * NH + h], v);
}

__global__ void edge_exp_k(const int* __restrict__ dst,
                           float* __restrict__ ebuf, const float* __restrict__ m,
                           float* __restrict__ den, int E)
{
    int idx = blockIdx.x * blockDim.x + threadIdx.x;
    if (idx >= E * NH) return;
    int e = idx >> 2, h = idx & 3;
    int d = dst[e];
    float ex = expf(ebuf[idx] - m[d * NH + h]);
    ebuf[idx] = ex;
    atomicAdd(&den[d * NH + h], ex);
}

__global__ void gat_agg_k(const int* __restrict__ src, const int* __restrict__ dst,
                          const float* __restrict__ ebuf, const float* __restrict__ den,
                          const float* __restrict__ z, float* __restrict__ hcat, int E)
{
    int w = (blockIdx.x * blockDim.x + threadIdx.x) >> 5;
    if (w >= E) return;
    int lane = threadIdx.x & 31;
    int s = src[w], d = dst[w];
    int head = lane >> 3;
    int d0 = lane * 4;
    float alpha = ebuf[w * NH + head] / den[d * NH + head];
    float4 zv = *(const float4*)(z + (long)s * D + d0);
    red_add_v4(hcat + (long)d * 256 + 128 + d0,
               alpha * zv.x, alpha * zv.y, alpha * zv.z, alpha * zv.w);
}

// ---------------- launcher -------------------------------------------------------
extern "C" void kernel_launch(void* const* d_in, const int* in_sizes, int n_in,
                              void* d_out, int out_size)
{
    const float* feat   = (const float*)d_in[0];
    const int*   src    = (const int*)  d_in[1];
    const int*   dst    = (const int*)  d_in[2];
    const int*   et     = (const int*)  d_in[3];
    const float* tw     = (const float*)d_in[4];
    const float* W_rel  = (const float*)d_in[5];
    const float* b_rel  = (const float*)d_in[6];
    const float* W_loop = (const float*)d_in[7];
    const float* W_gat  = (const float*)d_in[8];
    const float* attn_l = (const float*)d_in[9];
    const float* attn_r = (const float*)d_in[10];
    const float* b_gat  = (const float*)d_in[11];
    const float* W_fuse = (const float*)d_in[12];
    const float* b_fuse = (const float*)d_in[13];
    const float* W_gate = (const float*)d_in[14];
    const float* b_gate = (const float*)d_in[15];

    const int Nn = in_sizes[0] / D;
    const int E  = in_sizes[1];

    cudaFuncSetAttribute(bf_gemm<0, false>, cudaFuncAttributeMaxDynamicSharedMemorySize, SMEM_BYTES);
    cudaFuncSetAttribute(bf_gemm<0, true>,  cudaFuncAttributeMaxDynamicSharedMemorySize, SMEM_BYTES);
    cudaFuncSetAttribute(bf_gemm<2, false>, cudaFuncAttributeMaxDynamicSharedMemorySize, SMEM_BYTES);
    cudaFuncSetAttribute(bf_gemm<3, false>, cudaFuncAttributeMaxDynamicSharedMemorySize, SMEM_BYTES);

    float *ht, *hcat, *h, *z, *el, *er, *m, *den, *ebuf, *tws;
    __nv_bfloat16 *xhi, *xlo;
    uint32_t *whi, *wlo;
    cudaGetSymbolAddress((void**)&ht,   g_ht);
    cudaGetSymbolAddress((void**)&hcat, g_hcat);
    cudaGetSymbolAddress((void**)&h,    g_h);
    cudaGetSymbolAddress((void**)&z,    g_z);
    cudaGetSymbolAddress((void**)&el,   g_el);
    cudaGetSymbolAddress((void**)&er,   g_er);
    cudaGetSymbolAddress((void**)&m,    g_m);
    cudaGetSymbolAddress((void**)&den,  g_den);
    cudaGetSymbolAddress((void**)&ebuf, g_ebuf);
    cudaGetSymbolAddress((void**)&tws,  g_twsum);
    cudaGetSymbolAddress((void**)&xhi,  g_xhi);
    cudaGetSymbolAddress((void**)&xlo,  g_xlo);
    cudaGetSymbolAddress((void**)&whi,  g_wpk_hi);
    cudaGetSymbolAddress((void**)&wlo,  g_wpk_lo);

    const int MB = (Nn + 127) / 128;
    const int TPB = 256;
    const int eh_blocks    = (E * NH + TPB - 1) / TPB;
    const int ewarp_blocks = (E * 32 + TPB - 1) / TPB;
    const int nd_blocks    = (Nn * D + TPB - 1) / TPB;
    const int nh_blocks    = (Nn * NH + TPB - 1) / TPB;
    const int cvt128_blocks = (Nn * D / 4 + TPB - 1) / TPB;
    const int cvt256_blocks = (Nn * 2 * D / 4 + TPB - 1) / TPB;

    zero_scalar_k<<<1, 1>>>(tws);
    reduce_sum_k<<<256, 256>>>(tw, tws, E);

    // static weights: W_fuse (K=256 -> 128 packed rows), W_gate (first 128 rows)
    cvt_wt_k<<<(128 * 128 + TPB - 1) / TPB, TPB>>>(W_fuse, whi + 1152 * 128, wlo + 1152 * 128, 128);
    cvt_wt_k<<<(64 * 128 + TPB - 1) / TPB, TPB>>>(W_gate, whi + 1280 * 128, wlo + 1280 * 128, 64);

    const float* X = feat;
    for (int l = 0; l < NL; l++) {
        const float* Wrel_l  = W_rel  + (long)l * R * D * D;
        const float* Wloop_l = W_loop + (long)l * D * D;
        const float* Wgat_l  = W_gat  + (long)l * D * D;
        const float* brel_l  = b_rel  + l * D;
        const float* bgat_l  = b_gat  + l * D;
        const float* al_l    = attn_l + l * NH * DH;
        const float* ar_l    = attn_r + l * NH * DH;

        // convert activations and this layer's weights
        cvt_act_k<<<cvt128_blocks, TPB>>>(X, xhi, xlo, Nn * D / 4);
        cvt_wt_k<<<(1024 * 128 + TPB - 1) / TPB, TPB>>>(Wrel_l, whi, wlo, 1024);
        cvt_wt_k<<<(64 * 128 + TPB - 1) / TPB, TPB>>>(Wloop_l, whi + 1024 * 128, wlo + 1024 * 128, 64);
        cvt_wt_k<<<(64 * 128 + TPB - 1) / TPB, TPB>>>(Wgat_l,  whi + 1088 * 128, wlo + 1088 * 128, 64);

        // 1) ht[:, r, :] = X @ W_rel[l, r]
        bf_gemm<0, false><<<dim3(MB, R), 512, SMEM_BYTES>>>(
            xhi, xlo, D, whi, wlo, 64 * 128,
            ht, R * D, (long)D, nullptr, 0,
            Nn, D, nullptr, nullptr, nullptr, nullptr, nullptr, 0.f);
        // 2) dual: y0: hcat[:,0:128] = X@W_loop + b_rel ; y1: z = X@W_gat
        bf_gemm<0, true><<<dim3(MB, 2), 512, SMEM_BYTES>>>(
            xhi, xlo, D, whi + 1024 * 128, wlo + 1024 * 128, 64 * 128,
            hcat, 2 * D, 0, z, D,
            Nn, D, brel_l, nullptr, nullptr, nullptr, nullptr, 0.f);
        // 3) init
        init_gat_k<<<nd_blocks, TPB>>>(hcat, bgat_l, Nn);
        init_mh_k<<<nh_blocks, TPB>>>(m, den, Nn);
        // 4) RelConv scatter
        scatter_rel_k<<<ewarp_blocks, TPB>>>(ht, src, dst, et, hcat, E);
        // 5-8) GAT edge softmax + aggregation
        eler_k<<<nh_blocks, TPB>>>(z, al_l, ar_l, el, er, Nn);
        edge_max_k<<<eh_blocks, TPB>>>(src, dst, el, er, ebuf, m, E);
        edge_exp_k<<<eh_blocks, TPB>>>(dst, ebuf, m, den, E);
        gat_agg_k<<<ewarp_blocks, TPB>>>(src, dst, ebuf, den, z, hcat, E);

        // 9) fuse (+ gate at layer 0)
        float* out_l = (l == NL - 1) ? (float*)d_out : h;
        cvt_act_k<<<cvt256_blocks, TPB>>>(hcat, xhi, xlo, Nn * 2 * D / 4);
        if (l == 0) {
            bf_gemm<0, false><<<dim3(MB, 1), 512, SMEM_BYTES>>>(
                xhi, xlo, 2 * D, whi + 1152 * 128, wlo + 1152 * 128, 0,
                z, D, 0, nullptr, 0,
                Nn, 2 * D, b_fuse, nullptr, nullptr, nullptr, nullptr, 0.f);
            cvt_act_k<<<cvt128_blocks, TPB>>>(z, xhi, xlo, Nn * D / 4);
            bf_gemm<3, false><<<dim3(MB, 1), 512, SMEM_BYTES>>>(
                xhi, xlo, D, whi + 1280 * 128, wlo + 1280 * 128, 0,
                out_l, D, 0, nullptr, 0,
                Nn, D, b_gate, nullptr, z, W_gate + (long)D * D,
                tws, 1.0f / (float)E);
        } else {
            bf_gemm<2, false><<<dim3(MB, 1), 512, SMEM_BYTES>>>(
                xhi, xlo, 2 * D, whi + 1152 * 128, wlo + 1152 * 128, 0,
                out_l, D, 0, nullptr, 0,
                Nn, 2 * D, b_fuse, nullptr, nullptr, nullptr, nullptr, 0.f);
        }
        X = h;
    }
}

// round 4
// speedup vs baseline: 2.0929x; 1.0569x over previous
#include <cuda_runtime.h>
#include <cuda_bf16.h>
#include <math.h>
#include <stdint.h>

// Problem constants: N=30000, E=480000, D=128, R=16, H=4, DH=32, L=3
#define MAXN 30000
#define MAXE 480000
#define D 128
#define R 16
#define NH 4
#define DH 32
#define NL 3

// ---------------- scratch ----------------------------------------------------
__device__ float g_ht[(long)MAXN * (R * D)];
__device__ float g_hcat[(long)MAXN * (2 * D)];
__device__ float g_z[(long)MAXN * D];
__device__ float g_el[MAXN * NH];
__device__ float g_er[MAXN * NH];
__device__ float g_den[MAXN * NH];
__device__ float g_ebuf[MAXE * NH];
__device__ float g_twsum;
// two bf16 hi/lo activation buffer pairs (max K = 256)
__device__ __nv_bfloat16 g_ahi[(long)MAXN * 256];
__device__ __nv_bfloat16 g_alo[(long)MAXN * 256];
__device__ __nv_bfloat16 g_bhi[(long)MAXN * 256];
__device__ __nv_bfloat16 g_blo[(long)MAXN * 256];
// packed bf16-pair weights, rows of 128 words (column-permuted for LDS.128):
//   [0,3072): W_rel (3 layers x 16 x 64 rows)
//   [3072,3264): W_loop (3 x 64)   [3264,3456): W_gat (3 x 64)
//   [3456,3584): W_fuse (128)      [3584,3648): W_gate (64)
#define WPK_ROWS 3648
__device__ uint32_t g_wpk_hi[WPK_ROWS * 128];
__device__ uint32_t g_wpk_lo[WPK_ROWS * 128];

// ---------------- helpers ----------------------------------------------------
__device__ __forceinline__ void red_add_v4(float* p, float x, float y, float z, float w) {
    asm volatile("red.global.add.v4.f32 [%0], {%1, %2, %3, %4};"
                 :: "l"(p), "f"(x), "f"(y), "f"(z), "f"(w) : "memory");
}
__device__ __forceinline__ void ldsm4(uint32_t r[4], uint32_t addr) {
    asm volatile("ldmatrix.sync.aligned.m8n8.x4.shared.b16 {%0,%1,%2,%3}, [%4];"
                 : "=r"(r[0]), "=r"(r[1]), "=r"(r[2]), "=r"(r[3]) : "r"(addr));
}
__device__ __forceinline__ void mma16816(float c[4], const uint32_t a[4], const uint32_t b[2]) {
    asm volatile("mma.sync.aligned.m16n8k16.row.col.f32.bf16.bf16.f32 "
                 "{%0,%1,%2,%3}, {%4,%5,%6,%7}, {%8,%9}, {%0,%1,%2,%3};"
                 : "+f"(c[0]), "+f"(c[1]), "+f"(c[2]), "+f"(c[3])
                 : "r"(a[0]), "r"(a[1]), "r"(a[2]), "r"(a[3]), "r"(b[0]), "r"(b[1]));
}
__device__ __forceinline__ void cp16(uint32_t dst, const void* src, bool pred) {
    int sz = pred ? 16 : 0;
    asm volatile("cp.async.cg.shared.global [%0], [%1], 16, %2;"
                 :: "r"(dst), "l"(src), "r"(sz));
}
__device__ __forceinline__ void cp_commit() { asm volatile("cp.async.commit_group;"); }
template <int NN> __device__ __forceinline__ void cp_wait() {
    asm volatile("cp.async.wait_group %0;" :: "n"(NN));
}

// ---------------- conversion kernels ------------------------------------------
__global__ void cvt_act_k(const float* __restrict__ x,
                          __nv_bfloat16* __restrict__ hi, __nv_bfloat16* __restrict__ lo,
                          int total4)
{
    int i = blockIdx.x * blockDim.x + threadIdx.x;
    if (i >= total4) return;
    float4 v = ((const float4*)x)[i];
    __nv_bfloat16 h0 = __float2bfloat16_rn(v.x), h1 = __float2bfloat16_rn(v.y);
    __nv_bfloat16 h2 = __float2bfloat16_rn(v.z), h3 = __float2bfloat16_rn(v.w);
    __nv_bfloat162 H0; H0.x = h0; H0.y = h1;
    __nv_bfloat162 H1; H1.x = h2; H1.y = h3;
    ((__nv_bfloat162*)hi)[i * 2 + 0] = H0;
    ((__nv_bfloat162*)hi)[i * 2 + 1] = H1;
    __nv_bfloat162 L0, L1;
    L0.x = __float2bfloat16_rn(v.x - __bfloat162float(h0));
    L0.y = __float2bfloat16_rn(v.y - __bfloat162float(h1));
    L1.x = __float2bfloat16_rn(v.z - __bfloat162float(h2));
    L1.y = __float2bfloat16_rn(v.w - __bfloat162float(h3));
    ((__nv_bfloat162*)lo)[i * 2 + 0] = L0;
    ((__nv_bfloat162*)lo)[i * 2 + 1] = L1;
}

// W fp32 [2*k2max, 128] row-major -> packed k-pair words with permuted columns:
//  n' = (n&~31) | ((n&7)<<2) | ((n>>3)&3)   (so LDS.128 fetches 4 n-tile frags)
__global__ void cvt_wt_k(const float* __restrict__ W,
                         uint32_t* __restrict__ hi, uint32_t* __restrict__ lo, int k2max)
{
    int i = blockIdx.x * blockDim.x + threadIdx.x;
    if (i >= k2max * 128) return;
    int k2 = i >> 7, n = i & 127;
    float a = W[(2 * k2) * 128 + n];
    float b = W[(2 * k2 + 1) * 128 + n];
    __nv_bfloat16 ah = __float2bfloat16_rn(a), bh = __float2bfloat16_rn(b);
    __nv_bfloat162 H; H.x = ah; H.y = bh;
    __nv_bfloat162 Lw;
    Lw.x = __float2bfloat16_rn(a - __bfloat162float(ah));
    Lw.y = __float2bfloat16_rn(b - __bfloat162float(bh));
    int np = (n & ~31) | ((n & 7) << 2) | ((n >> 3) & 3);
    hi[k2 * 128 + np] = *(uint32_t*)&H;
    lo[k2 * 128 + np] = *(uint32_t*)&Lw;
}

// ---------------- bf16x3 tensor-core GEMM -------------------------------------
// CTA 128x128, BK=32, 512 threads (16 warps 4x4, warp tile 32x32), cp.async dbuf.
// EPI: 0 none/bias, 1 bias+relu, 2 temporal gate.  OUTM bit0: fp32 C, bit1: bf16 hi/lo.
#define AS_BUF 8192            // 128 rows * 64B
#define BS_BUF 8704            // 16 rows * 136 words * 4B
#define OFF_AHI 0
#define OFF_ALO (2 * AS_BUF)
#define OFF_BHI (4 * AS_BUF)
#define OFF_BLO (4 * AS_BUF + 2 * BS_BUF)
#define SMEM_BYTES (4 * AS_BUF + 4 * BS_BUF)   // 67584

template <int EPI, int OUTM, bool DUAL>
__global__ __launch_bounds__(512)
void bf_gemm(const __nv_bfloat16* __restrict__ Ahi, const __nv_bfloat16* __restrict__ Alo,
             int lda,
             const uint32_t* __restrict__ Bhi, const uint32_t* __restrict__ Blo, long bstr,
             float* __restrict__ C, int ldc, long cstr,
             float* __restrict__ C2, int ldc2,
             __nv_bfloat16* __restrict__ obhi, __nv_bfloat16* __restrict__ oblo,
             int M, int K,
             const float* __restrict__ bias, const float* __restrict__ bias2,
             const float* __restrict__ hcsrc,
             const float* __restrict__ gate_wlast,
             const float* __restrict__ tw_sum, float invE)
{
    extern __shared__ char sm[];
    const uint32_t smB = (uint32_t)__cvta_generic_to_shared(sm);

    const uint32_t* BhY = Bhi + (long)blockIdx.y * bstr;
    const uint32_t* BlY = Blo + (long)blockIdx.y * bstr;
    float* Cp; int ldcv; const float* biasv;
    if (DUAL && blockIdx.y == 1) { Cp = C2; ldcv = ldc2; biasv = bias2; }
    else { Cp = C + (long)blockIdx.y * cstr; ldcv = ldc; biasv = bias; }

    const int m0   = blockIdx.x * 128;
    const int tid  = threadIdx.x;
    const int lane = tid & 31;
    const int wid  = tid >> 5;
    const int grp  = lane >> 2;
    const int tig  = lane & 3;
    const int wm   = (wid >> 2) * 32;
    const int wn   = (wid & 3) * 32;      // word offset within B row

    // cp.async A: row=tid>>2, 16B chunk=tid&3, chunk-swizzled
    const int aRow = tid >> 2;
    const int aC   = tid & 3;
    const int aSC  = aC ^ ((aRow >> 1) & 3);
    const int gmA  = m0 + aRow;
    const bool aOk = gmA < M;
    const long aSrcOff = (long)(aOk ? gmA : 0) * lda + aC * 8;
    const uint32_t aDst = aRow * 64 + aSC * 16;
    // cp.async B: row=tid>>5 (0..15), col chunk=tid&31 ; smem row stride 544B
    const int bRow = tid >> 5;
    const int bC   = tid & 31;
    const uint32_t bDst = bRow * 544 + bC * 16;
    const int bSrcOff = bRow * 128 + bC * 4;

    auto issue = [&](int k0, int b) {
        cp16(smB + OFF_AHI + b * AS_BUF + aDst, Ahi + aSrcOff + k0, aOk);
        cp16(smB + OFF_ALO + b * AS_BUF + aDst, Alo + aSrcOff + k0, aOk);
        cp16(smB + OFF_BHI + b * BS_BUF + bDst, BhY + (k0 >> 1) * 128 + bSrcOff, true);
        cp16(smB + OFF_BLO + b * BS_BUF + bDst, BlY + (k0 >> 1) * 128 + bSrcOff, true);
        cp_commit();
    };

    float acc[2][4][4];
#pragma unroll
    for (int i = 0; i < 2; i++)
#pragma unroll
        for (int j = 0; j < 4; j++)
#pragma unroll
            for (int k = 0; k < 4; k++) acc[i][j][k] = 0.f;

    const int arow_l  = wm + (lane & 15);
    const int aShift  = (arow_l >> 1) & 3;
    const int aChunk0 = lane >> 4;
    const uint32_t aRowByte = arow_l * 64;

    const int nch = K >> 5;
    issue(0, 0);

    for (int c = 0; c < nch; c++) {
        const int b = c & 1;
        if (c + 1 < nch) issue((c + 1) << 5, b ^ 1);
        if (c + 1 < nch) cp_wait<1>(); else cp_wait<0>();
        __syncthreads();

        const char* bsH = sm + OFF_BHI + b * BS_BUF;
        const char* bsL = sm + OFF_BLO + b * BS_BUF;
#pragma unroll
        for (int kc = 0; kc < 2; kc++) {
            uint32_t ah[2][4], al[2][4];
#pragma unroll
            for (int mt = 0; mt < 2; mt++) {
                const int sc = ((kc * 2 + aChunk0) ^ aShift) * 16;
                uint32_t off = aRowByte + mt * 1024 + sc;
                ldsm4(ah[mt], smB + OFF_AHI + b * AS_BUF + off);
                ldsm4(al[mt], smB + OFF_ALO + b * AS_BUF + off);
            }
            const int r0 = kc * 8 + tig;
            const uint32_t bo0 = (uint32_t)((r0 * 136 + wn + grp * 4) << 2);
            const uint32_t bo1 = (uint32_t)(((r0 + 4) * 136 + wn + grp * 4) << 2);
            uint4 h0 = *(const uint4*)(bsH + bo0);
            uint4 h1 = *(const uint4*)(bsH + bo1);
            uint4 l0 = *(const uint4*)(bsL + bo0);
            uint4 l1 = *(const uint4*)(bsL + bo1);
            uint32_t bh[4][2], bl[4][2];
            bh[0][0] = h0.x; bh[1][0] = h0.y; bh[2][0] = h0.z; bh[3][0] = h0.w;
            bh[0][1] = h1.x; bh[1][1] = h1.y; bh[2][1] = h1.z; bh[3][1] = h1.w;
            bl[0][0] = l0.x; bl[1][0] = l0.y; bl[2][0] = l0.z; bl[3][0] = l0.w;
            bl[0][1] = l1.x; bl[1][1] = l1.y; bl[2][1] = l1.z; bl[3][1] = l1.w;
#pragma unroll
            for (int mt = 0; mt < 2; mt++)
#pragma unroll
                for (int nt = 0; nt < 4; nt++) {
                    mma16816(acc[mt][nt], ah[mt], bh[nt]);
                    mma16816(acc[mt][nt], al[mt], bh[nt]);
                    mma16816(acc[mt][nt], ah[mt], bl[nt]);
                }
        }
        __syncthreads();
    }

    // ---------------- epilogue ----------------
    float twm = 0.0f;
    if (EPI == 2) twm = tw_sum[0] * invE;

#pragma unroll
    for (int mt = 0; mt < 2; mt++)
#pragma unroll
        for (int nt = 0; nt < 4; nt++) {
            const int n = wn + nt * 8 + 2 * tig;
#pragma unroll
            for (int half = 0; half < 2; half++) {
                const int gm = m0 + wm + mt * 16 + grp + half * 8;
                if (gm >= M) continue;
                float v0 = acc[mt][nt][half * 2 + 0];
                float v1 = acc[mt][nt][half * 2 + 1];
                if (biasv) { v0 += biasv[n]; v1 += biasv[n + 1]; }
                if (EPI == 1) { v0 = fmaxf(v0, 0.f); v1 = fmaxf(v1, 0.f); }
                if (EPI == 2) {
                    float g0 = v0 + twm * gate_wlast[n];
                    float g1 = v1 + twm * gate_wlast[n + 1];
                    g0 = 1.0f / (1.0f + expf(-g0));
                    g1 = 1.0f / (1.0f + expf(-g1));
                    float2 hc = *(const float2*)(hcsrc + (long)gm * 128 + n);
                    v0 = fmaxf(hc.x * g0, 0.f);
                    v1 = fmaxf(hc.y * g1, 0.f);
                }
                if (OUTM & 1) {
                    float2 o; o.x = v0; o.y = v1;
                    *(float2*)(Cp + (long)gm * ldcv + n) = o;
                }
                if (OUTM & 2) {
                    __nv_bfloat162 H, Lw;
                    H.x = __float2bfloat16_rn(v0);
                    H.y = __float2bfloat16_rn(v1);
                    Lw.x = __float2bfloat16_rn(v0 - __bfloat162float(H.x));
                    Lw.y = __float2bfloat16_rn(v1 - __bfloat162float(H.y));
                    *(__nv_bfloat162*)(obhi + (long)gm * 128 + n) = H;
                    *(__nv_bfloat162*)(oblo + (long)gm * 128 + n) = Lw;
                }
            }
        }
}

// ---------------- small kernels ------------------------------------------------
__global__ void zero_scalar_k(float* p) { *p = 0.0f; }

__global__ void reduce_sum_k(const float* __restrict__ x, float* out, int n) {
    float s = 0.0f;
    for (int i = blockIdx.x * blockDim.x + threadIdx.x; i < n; i += gridDim.x * blockDim.x)
        s += x[i];
#pragma unroll
    for (int o = 16; o > 0; o >>= 1) s += __shfl_xor_sync(0xFFFFFFFFu, s, o);
    __shared__ float ws[8];
    if ((threadIdx.x & 31) == 0) ws[threadIdx.x >> 5] = s;
    __syncthreads();
    if (threadIdx.x < 32) {
        s = (threadIdx.x < (blockDim.x >> 5)) ? ws[threadIdx.x] : 0.0f;
#pragma unroll
        for (int o = 4; o > 0; o >>= 1) s += __shfl_xor_sync(0xFFFFFFFFu, s, o);
        if (threadIdx.x == 0) atomicAdd(out, s);
    }
}

// hcat[:,128:256] = b_gat ; den = 0
__global__ void init_k(float* __restrict__ hcat, const float* __restrict__ bgat,
                       float* __restrict__ den, int n)
{
    int idx = blockIdx.x * blockDim.x + threadIdx.x;
    if (idx < n * D) {
        int node = idx >> 7, d = idx & 127;
        hcat[(long)node * 256 + 128 + d] = bgat[d];
    }
    if (idx < n * NH) den[idx] = 0.0f;
}

__global__ void eler_k(const float* __restrict__ z,
                       const float* __restrict__ al, const float* __restrict__ ar,
                       float* __restrict__ el, float* __restrict__ er, int n)
{
    int idx = blockIdx.x * blockDim.x + threadIdx.x;
    if (idx >= n * NH) return;
    int node = idx >> 2, h = idx & 3;
    const float* zr = z + (long)node * D + h * DH;
    const float* a = al + h * DH;
    const float* b = ar + h * DH;
    float sl = 0.0f, sr = 0.0f;
#pragma unroll
    for (int k = 0; k < DH; k++) {
        float zv = zr[k];
        sl = fmaf(zv, __ldg(a + k), sl);
        sr = fmaf(zv, __ldg(b + k), sr);
    }
    el[idx] = sl; er[idx] = sr;
}

// leaky-relu + exp + segment-sum in one pass (softmax max-shift dropped: |e| small)
__global__ void edge_exp_k(const int* __restrict__ src, const int* __restrict__ dst,
                           const float* __restrict__ el, const float* __restrict__ er,
                           float* __restrict__ ebuf, float* __restrict__ den, int E)
{
    int idx = blockIdx.x * blockDim.x + threadIdx.x;
    if (idx >= E * NH) return;
    int e = idx >> 2, h = idx & 3;
    int s = src[e], d = dst[e];
    float v = el[s * NH + h] + er[d * NH + h];
    v = (v >= 0.0f) ? v : 0.2f * v;
    float ex = expf(v);
    ebuf[idx] = ex;
    atomicAdd(&den[d * NH + h], ex);
}

// combined: warp per edge does RelConv scatter AND GAT weighted aggregation
__global__ void scatter_both_k(const float* __restrict__ ht,
                               const int* __restrict__ src, const int* __restrict__ dst,
                               const int* __restrict__ et,
                               const float* __restrict__ ebuf, const float* __restrict__ den,
                               const float* __restrict__ z,
                               float* __restrict__ hcat, int E)
{
    int w = (blockIdx.x * blockDim.x + threadIdx.x) >> 5;
    if (w >= E) return;
    int lane = threadIdx.x & 31;
    int s = src[w], d = dst[w], r = et[w];
    int d0 = lane * 4;
    float4 v = *(const float4*)(ht + (long)s * 2048 + r * 128 + d0);
    red_add_v4(hcat + (long)d * 256 + d0, v.x, v.y, v.z, v.w);
    int head = lane >> 3;
    float alpha = ebuf[w * NH + head] / den[d * NH + head];
    float4 zv = *(const float4*)(z + (long)s * D + d0);
    red_add_v4(hcat + (long)d * 256 + 128 + d0,
               alpha * zv.x, alpha * zv.y, alpha * zv.z, alpha * zv.w);
}

// ---------------- launcher -------------------------------------------------------
extern "C" void kernel_launch(void* const* d_in, const int* in_sizes, int n_in,
                              void* d_out, int out_size)
{
    const float* feat   = (const float*)d_in[0];
    const int*   src    = (const int*)  d_in[1];
    const int*   dst    = (const int*)  d_in[2];
    const int*   et     = (const int*)  d_in[3];
    const float* tw     = (const float*)d_in[4];
    const float* W_rel  = (const float*)d_in[5];
    const float* b_rel  = (const float*)d_in[6];
    const float* W_loop = (const float*)d_in[7];
    const float* W_gat  = (const float*)d_in[8];
    const float* attn_l = (const float*)d_in[9];
    const float* attn_r = (const float*)d_in[10];
    const float* b_gat  = (const float*)d_in[11];
    const float* W_fuse = (const float*)d_in[12];
    const float* b_fuse = (const float*)d_in[13];
    const float* W_gate = (const float*)d_in[14];
    const float* b_gate = (const float*)d_in[15];

    const int Nn = in_sizes[0] / D;
    const int E  = in_sizes[1];

    cudaFuncSetAttribute(bf_gemm<0,1,false>, cudaFuncAttributeMaxDynamicSharedMemorySize, SMEM_BYTES);
    cudaFuncSetAttribute(bf_gemm<0,1,true>,  cudaFuncAttributeMaxDynamicSharedMemorySize, SMEM_BYTES);
    cudaFuncSetAttribute(bf_gemm<0,3,false>, cudaFuncAttributeMaxDynamicSharedMemorySize, SMEM_BYTES);
    cudaFuncSetAttribute(bf_gemm<2,2,false>, cudaFuncAttributeMaxDynamicSharedMemorySize, SMEM_BYTES);
    cudaFuncSetAttribute(bf_gemm<1,2,false>, cudaFuncAttributeMaxDynamicSharedMemorySize, SMEM_BYTES);
    cudaFuncSetAttribute(bf_gemm<1,1,false>, cudaFuncAttributeMaxDynamicSharedMemorySize, SMEM_BYTES);

    float *ht, *hcat, *z, *el, *er, *den, *ebuf, *tws;
    __nv_bfloat16 *Ahi, *Alo, *Bhi_a, *Blo_a;
    uint32_t *whi, *wlo;
    cudaGetSymbolAddress((void**)&ht,   g_ht);
    cudaGetSymbolAddress((void**)&hcat, g_hcat);
    cudaGetSymbolAddress((void**)&z,    g_z);
    cudaGetSymbolAddress((void**)&el,   g_el);
    cudaGetSymbolAddress((void**)&er,   g_er);
    cudaGetSymbolAddress((void**)&den,  g_den);
    cudaGetSymbolAddress((void**)&ebuf, g_ebuf);
    cudaGetSymbolAddress((void**)&tws,  g_twsum);
    cudaGetSymbolAddress((void**)&Ahi,  g_ahi);
    cudaGetSymbolAddress((void**)&Alo,  g_alo);
    cudaGetSymbolAddress((void**)&Bhi_a, g_bhi);
    cudaGetSymbolAddress((void**)&Blo_a, g_blo);
    cudaGetSymbolAddress((void**)&whi,  g_wpk_hi);
    cudaGetSymbolAddress((void**)&wlo,  g_wpk_lo);

    const int MB = (Nn + 127) / 128;
    const int TPB = 256;
    const int eh_blocks    = (E * NH + TPB - 1) / TPB;
    const int ewarp_blocks = (E * 32 + TPB - 1) / TPB;
    const int nd_blocks    = (Nn * D + TPB - 1) / TPB;
    const int nh_blocks    = (Nn * NH + TPB - 1) / TPB;
    const int cvt128_blocks = (Nn * D / 4 + TPB - 1) / TPB;
    const int cvt256_blocks = (Nn * 2 * D / 4 + TPB - 1) / TPB;

    zero_scalar_k<<<1, 1>>>(tws);
    reduce_sum_k<<<256, 256>>>(tw, tws, E);

    // convert ALL weights once (column-permuted, k-paired)
    cvt_wt_k<<<(3072 * 128 + TPB - 1) / TPB, TPB>>>(W_rel,  whi,              wlo,              3072);
    cvt_wt_k<<<(192 * 128 + TPB - 1) / TPB, TPB>>>(W_loop, whi + 3072 * 128, wlo + 3072 * 128, 192);
    cvt_wt_k<<<(192 * 128 + TPB - 1) / TPB, TPB>>>(W_gat,  whi + 3264 * 128, wlo + 3264 * 128, 192);
    cvt_wt_k<<<(128 * 128 + TPB - 1) / TPB, TPB>>>(W_fuse, whi + 3456 * 128, wlo + 3456 * 128, 128);
    cvt_wt_k<<<(64 * 128 + TPB - 1) / TPB, TPB>>>(W_gate, whi + 3584 * 128, wlo + 3584 * 128, 64);

    // layer-0 input activations
    cvt_act_k<<<cvt128_blocks, TPB>>>(feat, Ahi, Alo, Nn * D / 4);

    // buffer schedule: cur(128) -> [GEMMs] ; cvt(hcat)->other(256) ; fuse -> writes bf16
    __nv_bfloat16 *cur_hi = Ahi, *cur_lo = Alo;
    __nv_bfloat16 *oth_hi = Bhi_a, *oth_lo = Blo_a;

    for (int l = 0; l < NL; l++) {
        const float* brel_l = b_rel  + l * D;
        const float* bgat_l = b_gat  + l * D;
        const float* al_l   = attn_l + l * NH * DH;
        const float* ar_l   = attn_r + l * NH * DH;
        const uint32_t* wrel_hi  = whi + (long)(l * 1024) * 128;
        const uint32_t* wrel_lo  = wlo + (long)(l * 1024) * 128;
        const uint32_t* wloop_hi = whi + (long)(3072 + l * 64) * 128;
        const uint32_t* wloop_lo = wlo + (long)(3072 + l * 64) * 128;

        // 1) ht[:, r, :] = X @ W_rel[l, r]
        bf_gemm<0,1,false><<<dim3(MB, R), 512, SMEM_BYTES>>>(
            cur_hi, cur_lo, D, wrel_hi, wrel_lo, 64 * 128,
            ht, R * D, (long)D, nullptr, 0, nullptr, nullptr,
            Nn, D, nullptr, nullptr, nullptr, nullptr, nullptr, 0.f);
        // 2) dual: y0: hcat[:,0:128] = X@W_loop + b_rel ; y1: z = X@W_gat
        //    (W_gat block sits 192 packed rows after W_loop block => bstr = 192*128)
        bf_gemm<0,1,true><<<dim3(MB, 2), 512, SMEM_BYTES>>>(
            cur_hi, cur_lo, D, wloop_hi, wloop_lo, (long)192 * 128,
            hcat, 2 * D, 0, z, D, nullptr, nullptr,
            Nn, D, brel_l, nullptr, nullptr, nullptr, nullptr, 0.f);
        // 3) init hcat gat-half + den
        init_k<<<nd_blocks, TPB>>>(hcat, bgat_l, den, Nn);
        // 4) attention logits
        eler_k<<<nh_blocks, TPB>>>(z, al_l, ar_l, el, er, Nn);
        // 5) leaky+exp+segment-sum (no max pass)
        edge_exp_k<<<eh_blocks, TPB>>>(src, dst, el, er, ebuf, den, E);
        // 6) combined RelConv + GAT scatter
        scatter_both_k<<<ewarp_blocks, TPB>>>(ht, src, dst, et, ebuf, den, z, hcat, E);
        // 7) convert hcat (K=256) into the other buffer
        cvt_act_k<<<cvt256_blocks, TPB>>>(hcat, oth_hi, oth_lo, Nn * 2 * D / 4);

        // 8) fuse (+ gate at layer 0)
        if (l == 0) {
            // hc = hcat@W_fuse + b_fuse -> z (fp32 for gating) + bf16 into cur
            bf_gemm<0,3,false><<<dim3(MB, 1), 512, SMEM_BYTES>>>(
                oth_hi, oth_lo, 2 * D, whi + (long)3456 * 128, wlo + (long)3456 * 128, 0,
                z, D, 0, nullptr, 0, cur_hi, cur_lo,
                Nn, 2 * D, b_fuse, nullptr, nullptr, nullptr, nullptr, 0.f);
            // out = relu(hc * sigmoid(hc@Wg + twm*Wg[D] + b_gate)) -> bf16 into oth
            bf_gemm<2,2,false><<<dim3(MB, 1), 512, SMEM_BYTES>>>(
                cur_hi, cur_lo, D, whi + (long)3584 * 128, wlo + (long)3584 * 128, 0,
                nullptr, 0, 0, nullptr, 0, oth_hi, oth_lo,
                Nn, D, b_gate, nullptr, z, W_gate + (long)D * D,
                tws, 1.0f / (float)E);
            // next layer input = oth
            __nv_bfloat16* t;
            t = cur_hi; cur_hi = oth_hi; oth_hi = t;
            t = cur_lo; cur_lo = oth_lo; oth_lo = t;
        } else if (l < NL - 1) {
            // relu(hcat@W_fuse + b_fuse) -> bf16 into cur (cur's data already consumed)
            bf_gemm<1,2,false><<<dim3(MB, 1), 512, SMEM_BYTES>>>(
                oth_hi, oth_lo, 2 * D, whi + (long)3456 * 128, wlo + (long)3456 * 128, 0,
                nullptr, 0, 0, nullptr, 0, cur_hi, cur_lo,
                Nn, 2 * D, b_fuse, nullptr, nullptr, nullptr, nullptr, 0.f);
        } else {
            // final layer -> fp32 d_out
            bf_gemm<1,1,false><<<dim3(MB, 1), 512, SMEM_BYTES>>>(
                oth_hi, oth_lo, 2 * D, whi + (long)3456 * 128, wlo + (long)3456 * 128, 0,
                (float*)d_out, D, 0, nullptr, 0, nullptr, nullptr,
                Nn, 2 * D, b_fuse, nullptr, nullptr, nullptr, nullptr, 0.f);
        }
    }
}

// round 5
// speedup vs baseline: 2.2258x; 1.0635x over previous
#include <cuda_runtime.h>
#include <cuda_bf16.h>
#include <math.h>
#include <stdint.h>

// Problem constants: N=30000, E=480000, D=128, R=16, H=4, DH=32, L=3
#define MAXN 30000
#define MAXE 480000
#define D 128
#define R 16
#define NH 4
#define DH 32
#define NL 3
#define NKMAX (MAXN * (R + 1))   // rel keys + dst keys

// ---------------- scratch ----------------------------------------------------
__device__ float g_hcat[(long)MAXN * (2 * D)];
__device__ float g_z[(long)MAXN * D];
__device__ float g_el[MAXN * NH];
__device__ float g_er[MAXN * NH];
__device__ float g_twsum;
// CSR machinery
__device__ int g_cnt[NKMAX];
__device__ int g_off[NKMAX + 1];
__device__ int g_cur[NKMAX];
__device__ int g_btot[512];
__device__ int g_buf[2 * MAXE];          // [0,E): dst per rel-key slot; [E,2E): src per dst-key slot
// two bf16 hi/lo activation buffer pairs (max K = 256)
__device__ __nv_bfloat16 g_ahi[(long)MAXN * 256];
__device__ __nv_bfloat16 g_alo[(long)MAXN * 256];
__device__ __nv_bfloat16 g_bhi[(long)MAXN * 256];
__device__ __nv_bfloat16 g_blo[(long)MAXN * 256];
// packed bf16-pair weights, rows of 128 words (column-permuted for LDS.128):
//   [0,3072): W_rel (3 layers x 16 x 64 rows)
//   [3072,3264): W_loop (3 x 64)   [3264,3456): W_gat (3 x 64)
//   [3456,3584): W_fuse (128)      [3584,3648): W_gate (64)
#define WPK_ROWS 3648
__device__ uint32_t g_wpk_hi[WPK_ROWS * 128];
__device__ uint32_t g_wpk_lo[WPK_ROWS * 128];

// ---------------- helpers ----------------------------------------------------
__device__ __forceinline__ void red_add_v2(float* p, float x, float y) {
    asm volatile("red.global.add.v2.f32 [%0], {%1, %2};"
                 :: "l"(p), "f"(x), "f"(y) : "memory");
}
__device__ __forceinline__ void ldsm4(uint32_t r[4], uint32_t addr) {
    asm volatile("ldmatrix.sync.aligned.m8n8.x4.shared.b16 {%0,%1,%2,%3}, [%4];"
                 : "=r"(r[0]), "=r"(r[1]), "=r"(r[2]), "=r"(r[3]) : "r"(addr));
}
__device__ __forceinline__ void mma16816(float c[4], const uint32_t a[4], const uint32_t b[2]) {
    asm volatile("mma.sync.aligned.m16n8k16.row.col.f32.bf16.bf16.f32 "
                 "{%0,%1,%2,%3}, {%4,%5,%6,%7}, {%8,%9}, {%0,%1,%2,%3};"
                 : "+f"(c[0]), "+f"(c[1]), "+f"(c[2]), "+f"(c[3])
                 : "r"(a[0]), "r"(a[1]), "r"(a[2]), "r"(a[3]), "r"(b[0]), "r"(b[1]));
}
__device__ __forceinline__ void cp16(uint32_t dst, const void* src, bool pred) {
    int sz = pred ? 16 : 0;
    asm volatile("cp.async.cg.shared.global [%0], [%1], 16, %2;"
                 :: "r"(dst), "l"(src), "r"(sz));
}
__device__ __forceinline__ void cp_commit() { asm volatile("cp.async.commit_group;"); }
template <int NN> __device__ __forceinline__ void cp_wait() {
    asm volatile("cp.async.wait_group %0;" :: "n"(NN));
}

// ---------------- conversion kernels ------------------------------------------
__global__ void cvt_act_k(const float* __restrict__ x,
                          __nv_bfloat16* __restrict__ hi, __nv_bfloat16* __restrict__ lo,
                          int total4)
{
    int i = blockIdx.x * blockDim.x + threadIdx.x;
    if (i >= total4) return;
    float4 v = ((const float4*)x)[i];
    __nv_bfloat16 h0 = __float2bfloat16_rn(v.x), h1 = __float2bfloat16_rn(v.y);
    __nv_bfloat16 h2 = __float2bfloat16_rn(v.z), h3 = __float2bfloat16_rn(v.w);
    __nv_bfloat162 H0; H0.x = h0; H0.y = h1;
    __nv_bfloat162 H1; H1.x = h2; H1.y = h3;
    ((__nv_bfloat162*)hi)[i * 2 + 0] = H0;
    ((__nv_bfloat162*)hi)[i * 2 + 1] = H1;
    __nv_bfloat162 L0, L1;
    L0.x = __float2bfloat16_rn(v.x - __bfloat162float(h0));
    L0.y = __float2bfloat16_rn(v.y - __bfloat162float(h1));
    L1.x = __float2bfloat16_rn(v.z - __bfloat162float(h2));
    L1.y = __float2bfloat16_rn(v.w - __bfloat162float(h3));
    ((__nv_bfloat162*)lo)[i * 2 + 0] = L0;
    ((__nv_bfloat162*)lo)[i * 2 + 1] = L1;
}

// W fp32 [2*k2max, 128] -> packed k-pair words, permuted cols for LDS.128
__global__ void cvt_wt_k(const float* __restrict__ W,
                         uint32_t* __restrict__ hi, uint32_t* __restrict__ lo, int k2max)
{
    int i = blockIdx.x * blockDim.x + threadIdx.x;
    if (i >= k2max * 128) return;
    int k2 = i >> 7, n = i & 127;
    float a = W[(2 * k2) * 128 + n];
    float b = W[(2 * k2 + 1) * 128 + n];
    __nv_bfloat16 ah = __float2bfloat16_rn(a), bh = __float2bfloat16_rn(b);
    __nv_bfloat162 H; H.x = ah; H.y = bh;
    __nv_bfloat162 Lw;
    Lw.x = __float2bfloat16_rn(a - __bfloat162float(ah));
    Lw.y = __float2bfloat16_rn(b - __bfloat162float(bh));
    int np = (n & ~31) | ((n & 7) << 2) | ((n >> 3) & 3);
    hi[k2 * 128 + np] = *(uint32_t*)&H;
    lo[k2 * 128 + np] = *(uint32_t*)&Lw;
}

// ---------------- CSR build ----------------------------------------------------
__global__ void zero_int_k(int* p, int n) {
    int i = blockIdx.x * blockDim.x + threadIdx.x;
    if (i < n) p[i] = 0;
}
__global__ void hist_k(const int* __restrict__ src, const int* __restrict__ dst,
                       const int* __restrict__ et, int* __restrict__ cnt, int E, int NR)
{
    int e = blockIdx.x * blockDim.x + threadIdx.x;
    if (e >= E) return;
    atomicAdd(&cnt[src[e] * R + et[e]], 1);
    atomicAdd(&cnt[NR + dst[e]], 1);
}
// 3-kernel exclusive scan (2048 elems/block)
__global__ void scan1_k(const int* __restrict__ cnt, int* __restrict__ off,
                        int* __restrict__ btot, int n)
{
    __shared__ int ws[8];
    int t = threadIdx.x;                    // 256
    int base = blockIdx.x * 2048 + t * 8;
    int v[8], s = 0;
#pragma unroll
    for (int i = 0; i < 8; i++) {
        int x = (base + i < n) ? cnt[base + i] : 0;
        v[i] = s; s += x;
    }
    int lane = t & 31, w = t >> 5;
    int inc = s;
#pragma unroll
    for (int o = 1; o < 32; o <<= 1) {
        int y = __shfl_up_sync(0xFFFFFFFFu, inc, o);
        if (lane >= o) inc += y;
    }
    if (lane == 31) ws[w] = inc;
    int texc = inc - s;
    __syncthreads();
    int wbase = 0;
#pragma unroll
    for (int i = 0; i < 8; i++) wbase += (i < w) ? ws[i] : 0;
#pragma unroll
    for (int i = 0; i < 8; i++)
        if (base + i < n) off[base + i] = wbase + texc + v[i];
    if (t == 255) btot[blockIdx.x] = wbase + inc;
}
__global__ void scan2_k(int* btot, int nb) {
    __shared__ int ws[8];
    int t = threadIdx.x;
    int xv = (t < nb) ? btot[t] : 0;
    int lane = t & 31, w = t >> 5;
    int inc = xv;
#pragma unroll
    for (int o = 1; o < 32; o <<= 1) {
        int y = __shfl_up_sync(0xFFFFFFFFu, inc, o);
        if (lane >= o) inc += y;
    }
    if (lane == 31) ws[w] = inc;
    __syncthreads();
    int wbase = 0;
#pragma unroll
    for (int i = 0; i < 8; i++) wbase += (i < w) ? ws[i] : 0;
    if (t < nb) btot[t] = wbase + inc - xv;
}
__global__ void scan3_k(int* __restrict__ off, int* __restrict__ cur,
                        const int* __restrict__ btot, int n, int total)
{
    int i = blockIdx.x * blockDim.x + threadIdx.x;
    if (i < n) {
        int o = off[i] + btot[i >> 11];
        off[i] = o; cur[i] = o;
    }
    if (i == 0) off[n] = total;
}
__global__ void fill_k(const int* __restrict__ src, const int* __restrict__ dst,
                       const int* __restrict__ et, int* __restrict__ cur,
                       int* __restrict__ buf, int E, int NR)
{
    int e = blockIdx.x * blockDim.x + threadIdx.x;
    if (e >= E) return;
    int s = src[e], d = dst[e];
    int p1 = atomicAdd(&cur[s * R + et[e]], 1);
    buf[p1] = d;
    int p2 = atomicAdd(&cur[NR + d], 1);
    buf[p2] = s;
}

// ---------------- bf16x3 tensor-core GEMM -------------------------------------
// MODE: 1 bias+relu->fp32 | 2 bias+relu->bf16 | 3 bias->fp32+bf16 |
//       4 temporal gate->bf16 | 5 dual (y0: bias->C ld256; y1: z + el/er) |
//       6 rel: scatter rows via CSR atomics (no store)
#define AS_BUF 8192
#define BS_BUF 8704
#define OFF_AHI 0
#define OFF_ALO (2 * AS_BUF)
#define OFF_BHI (4 * AS_BUF)
#define OFF_BLO (4 * AS_BUF + 2 * BS_BUF)
#define SMEM_BYTES (4 * AS_BUF + 4 * BS_BUF)

template <int MODE>
__global__ __launch_bounds__(512)
void bf_gemm(const __nv_bfloat16* __restrict__ Ahi, const __nv_bfloat16* __restrict__ Alo,
             int lda,
             const uint32_t* __restrict__ Bhi, const uint32_t* __restrict__ Blo, long bstr,
             float* __restrict__ C, int ldc,
             __nv_bfloat16* __restrict__ obhi, __nv_bfloat16* __restrict__ oblo,
             int M, int K,
             const float* __restrict__ bias,
             float* __restrict__ zout, float* __restrict__ el, float* __restrict__ er,
             const float* __restrict__ attnl, const float* __restrict__ attnr,
             const int* __restrict__ csr_off, const int* __restrict__ csr_buf,
             float* __restrict__ hcat,
             const float* __restrict__ hcsrc, const float* __restrict__ gate_wlast,
             const float* __restrict__ tw_sum, float invE)
{
    extern __shared__ char sm[];
    const uint32_t smB = (uint32_t)__cvta_generic_to_shared(sm);

    const uint32_t* BhY = Bhi + (long)blockIdx.y * bstr;
    const uint32_t* BlY = Blo + (long)blockIdx.y * bstr;

    const int m0   = blockIdx.x * 128;
    const int tid  = threadIdx.x;
    const int lane = tid & 31;
    const int wid  = tid >> 5;
    const int grp  = lane >> 2;
    const int tig  = lane & 3;
    const int wm   = (wid >> 2) * 32;
    const int wn   = (wid & 3) * 32;

    const int aRow = tid >> 2;
    const int aC   = tid & 3;
    const int aSC  = aC ^ ((aRow >> 1) & 3);
    const int gmA  = m0 + aRow;
    const bool aOk = gmA < M;
    const long aSrcOff = (long)(aOk ? gmA : 0) * lda + aC * 8;
    const uint32_t aDst = aRow * 64 + aSC * 16;
    const int bRow = tid >> 5;
    const int bC   = tid & 31;
    const uint32_t bDst = bRow * 544 + bC * 16;
    const int bSrcOff = bRow * 128 + bC * 4;

    auto issue = [&](int k0, int b) {
        cp16(smB + OFF_AHI + b * AS_BUF + aDst, Ahi + aSrcOff + k0, aOk);
        cp16(smB + OFF_ALO + b * AS_BUF + aDst, Alo + aSrcOff + k0, aOk);
        cp16(smB + OFF_BHI + b * BS_BUF + bDst, BhY + (k0 >> 1) * 128 + bSrcOff, true);
        cp16(smB + OFF_BLO + b * BS_BUF + bDst, BlY + (k0 >> 1) * 128 + bSrcOff, true);
        cp_commit();
    };

    float acc[2][4][4];
#pragma unroll
    for (int i = 0; i < 2; i++)
#pragma unroll
        for (int j = 0; j < 4; j++)
#pragma unroll
            for (int k = 0; k < 4; k++) acc[i][j][k] = 0.f;

    const int arow_l  = wm + (lane & 15);
    const int aShift  = (arow_l >> 1) & 3;
    const int aChunk0 = lane >> 4;
    const uint32_t aRowByte = arow_l * 64;

    const int nch = K >> 5;
    issue(0, 0);

    for (int c = 0; c < nch; c++) {
        const int b = c & 1;
        if (c + 1 < nch) issue((c + 1) << 5, b ^ 1);
        if (c + 1 < nch) cp_wait<1>(); else cp_wait<0>();
        __syncthreads();

        const char* bsH = sm + OFF_BHI + b * BS_BUF;
        const char* bsL = sm + OFF_BLO + b * BS_BUF;
#pragma unroll
        for (int kc = 0; kc < 2; kc++) {
            uint32_t ah[2][4], al[2][4];
#pragma unroll
            for (int mt = 0; mt < 2; mt++) {
                const int sc = ((kc * 2 + aChunk0) ^ aShift) * 16;
                uint32_t off = aRowByte + mt * 1024 + sc;
                ldsm4(ah[mt], smB + OFF_AHI + b * AS_BUF + off);
                ldsm4(al[mt], smB + OFF_ALO + b * AS_BUF + off);
            }
            const int r0 = kc * 8 + tig;
            const uint32_t bo0 = (uint32_t)((r0 * 136 + wn + grp * 4) << 2);
            const uint32_t bo1 = (uint32_t)(((r0 + 4) * 136 + wn + grp * 4) << 2);
            uint4 h0 = *(const uint4*)(bsH + bo0);
            uint4 h1 = *(const uint4*)(bsH + bo1);
            uint4 l0 = *(const uint4*)(bsL + bo0);
            uint4 l1 = *(const uint4*)(bsL + bo1);
            uint32_t bh[4][2], bl[4][2];
            bh[0][0] = h0.x; bh[1][0] = h0.y; bh[2][0] = h0.z; bh[3][0] = h0.w;
            bh[0][1] = h1.x; bh[1][1] = h1.y; bh[2][1] = h1.z; bh[3][1] = h1.w;
            bl[0][0] = l0.x; bl[1][0] = l0.y; bl[2][0] = l0.z; bl[3][0] = l0.w;
            bl[0][1] = l1.x; bl[1][1] = l1.y; bl[2][1] = l1.z; bl[3][1] = l1.w;
#pragma unroll
            for (int mt = 0; mt < 2; mt++)
#pragma unroll
                for (int nt = 0; nt < 4; nt++) {
                    mma16816(acc[mt][nt], ah[mt], bh[nt]);
                    mma16816(acc[mt][nt], al[mt], bh[nt]);
                    mma16816(acc[mt][nt], ah[mt], bl[nt]);
                }
        }
        __syncthreads();
    }

    // ================= epilogues =================
    if (MODE == 6) {
        // scatter rows of X @ W_rel[r] to hcat[dst, 0:128] via CSR((src=row, r=blockIdx.y))
        const int rY = blockIdx.y;
#pragma unroll
        for (int mt = 0; mt < 2; mt++)
#pragma unroll
            for (int half = 0; half < 2; half++) {
                const int gm = m0 + wm + mt * 16 + grp + half * 8;
                if (gm >= M) continue;
                float2 vv[4];
#pragma unroll
                for (int nt = 0; nt < 4; nt++) {
                    vv[nt].x = acc[mt][nt][half * 2 + 0];
                    vv[nt].y = acc[mt][nt][half * 2 + 1];
                }
                const int key = gm * R + rY;
                const int e0 = csr_off[key], e1 = csr_off[key + 1];
                for (int e = e0; e < e1; e++) {
                    const int d = csr_buf[e];
                    float* basep = hcat + (long)d * 256 + wn + 2 * tig;
#pragma unroll
                    for (int nt = 0; nt < 4; nt++)
                        red_add_v2(basep + nt * 8, vv[nt].x, vv[nt].y);
                }
            }
        return;
    }

    if (MODE == 5 && blockIdx.y == 1) {
        // z store + inline el/er (warp owns head h = wid&3)
        const int h = wid & 3;
#pragma unroll
        for (int mt = 0; mt < 2; mt++)
#pragma unroll
            for (int half = 0; half < 2; half++) {
                const int gm = m0 + wm + mt * 16 + grp + half * 8;
                const bool ok = gm < M;
                float elp = 0.f, erp = 0.f;
#pragma unroll
                for (int nt = 0; nt < 4; nt++) {
                    const int n = wn + nt * 8 + 2 * tig;
                    float v0 = acc[mt][nt][half * 2 + 0];
                    float v1 = acc[mt][nt][half * 2 + 1];
                    if (ok) {
                        float2 o; o.x = v0; o.y = v1;
                        *(float2*)(zout + (long)gm * 128 + n) = o;
                    }
                    const int dh = nt * 8 + 2 * tig;
                    elp += v0 * attnl[h * 32 + dh] + v1 * attnl[h * 32 + dh + 1];
                    erp += v0 * attnr[h * 32 + dh] + v1 * attnr[h * 32 + dh + 1];
                }
                elp += __shfl_xor_sync(0xFFFFFFFFu, elp, 1);
                elp += __shfl_xor_sync(0xFFFFFFFFu, elp, 2);
                erp += __shfl_xor_sync(0xFFFFFFFFu, erp, 1);
                erp += __shfl_xor_sync(0xFFFFFFFFu, erp, 2);
                if (ok && tig == 0) {
                    el[gm * NH + h] = elp;
                    er[gm * NH + h] = erp;
                }
            }
        return;
    }

    // standard store epilogues (MODE 1,2,3,4 and MODE5-y0)
    float twm = 0.0f;
    if (MODE == 4) twm = tw_sum[0] * invE;

#pragma unroll
    for (int mt = 0; mt < 2; mt++)
#pragma unroll
        for (int nt = 0; nt < 4; nt++) {
            const int n = wn + nt * 8 + 2 * tig;
#pragma unroll
            for (int half = 0; half < 2; half++) {
                const int gm = m0 + wm + mt * 16 + grp + half * 8;
                if (gm >= M) continue;
                float v0 = acc[mt][nt][half * 2 + 0];
                float v1 = acc[mt][nt][half * 2 + 1];
                if (bias) { v0 += bias[n]; v1 += bias[n + 1]; }
                if (MODE == 1 || MODE == 2) { v0 = fmaxf(v0, 0.f); v1 = fmaxf(v1, 0.f); }
                if (MODE == 4) {
                    float g0 = v0 + twm * gate_wlast[n];
                    float g1 = v1 + twm * gate_wlast[n + 1];
                    g0 = 1.0f / (1.0f + expf(-g0));
                    g1 = 1.0f / (1.0f + expf(-g1));
                    float2 hc = *(const float2*)(hcsrc + (long)gm * 128 + n);
                    v0 = fmaxf(hc.x * g0, 0.f);
                    v1 = fmaxf(hc.y * g1, 0.f);
                }
                if (MODE == 1 || MODE == 3 || MODE == 5) {
                    float2 o; o.x = v0; o.y = v1;
                    *(float2*)(C + (long)gm * ldc + n) = o;
                }
                if (MODE == 2 || MODE == 3 || MODE == 4) {
                    __nv_bfloat162 H, Lw;
                    H.x = __float2bfloat16_rn(v0);
                    H.y = __float2bfloat16_rn(v1);
                    Lw.x = __float2bfloat16_rn(v0 - __bfloat162float(H.x));
                    Lw.y = __float2bfloat16_rn(v1 - __bfloat162float(H.y));
                    *(__nv_bfloat162*)(obhi + (long)gm * 128 + n) = H;
                    *(__nv_bfloat162*)(oblo + (long)gm * 128 + n) = Lw;
                }
            }
        }
}

// ---------------- GAT gather (atomic-free) ---------------------------------------
__global__ void gat_gather_k(const int* __restrict__ off, const int* __restrict__ buf,
                             const float* __restrict__ el, const float* __restrict__ er,
                             const float* __restrict__ z, const float* __restrict__ bgat,
                             float* __restrict__ hcat, int n, int NR)
{
    int node = (blockIdx.x * blockDim.x + threadIdx.x) >> 5;
    if (node >= n) return;
    int lane = threadIdx.x & 31;
    int d0 = lane * 4;
    int head = lane >> 3;
    int e0 = off[NR + node], e1 = off[NR + node + 1];
    float erv = er[node * NH + head];
    float ax = 0.f, ay = 0.f, az = 0.f, aw = 0.f, sx = 0.f;
    for (int j = e0; j < e1; j++) {
        int s = buf[j];
        float v = el[s * NH + head] + erv;
        v = (v >= 0.f) ? v : 0.2f * v;
        float ex = expf(v);
        sx += ex;
        float4 zv = *(const float4*)(z + (long)s * 128 + d0);
        ax = fmaf(ex, zv.x, ax); ay = fmaf(ex, zv.y, ay);
        az = fmaf(ex, zv.z, az); aw = fmaf(ex, zv.w, aw);
    }
    float inv = (e1 > e0) ? (1.0f / sx) : 0.0f;
    float4 bg = *(const float4*)(bgat + d0);
    float4 o;
    o.x = fmaf(ax, inv, bg.x); o.y = fmaf(ay, inv, bg.y);
    o.z = fmaf(az, inv, bg.z); o.w = fmaf(aw, inv, bg.w);
    *(float4*)(hcat + (long)node * 256 + 128 + d0) = o;
}

// ---------------- misc ------------------------------------------------------------
__global__ void zero_scalar_k(float* p) { *p = 0.0f; }
__global__ void reduce_sum_k(const float* __restrict__ x, float* out, int n) {
    float s = 0.0f;
    for (int i = blockIdx.x * blockDim.x + threadIdx.x; i < n; i += gridDim.x * blockDim.x)
        s += x[i];
#pragma unroll
    for (int o = 16; o > 0; o >>= 1) s += __shfl_xor_sync(0xFFFFFFFFu, s, o);
    __shared__ float ws[8];
    if ((threadIdx.x & 31) == 0) ws[threadIdx.x >> 5] = s;
    __syncthreads();
    if (threadIdx.x < 32) {
        s = (threadIdx.x < (blockDim.x >> 5)) ? ws[threadIdx.x] : 0.0f;
#pragma unroll
        for (int o = 4; o > 0; o >>= 1) s += __shfl_xor_sync(0xFFFFFFFFu, s, o);
        if (threadIdx.x == 0) atomicAdd(out, s);
    }
}

// ---------------- launcher ----------------------------------------------------------
extern "C" void kernel_launch(void* const* d_in, const int* in_sizes, int n_in,
                              void* d_out, int out_size)
{
    const float* feat   = (const float*)d_in[0];
    const int*   src    = (const int*)  d_in[1];
    const int*   dst    = (const int*)  d_in[2];
    const int*   et     = (const int*)  d_in[3];
    const float* tw     = (const float*)d_in[4];
    const float* W_rel  = (const float*)d_in[5];
    const float* b_rel  = (const float*)d_in[6];
    const float* W_loop = (const float*)d_in[7];
    const float* W_gat  = (const float*)d_in[8];
    const float* attn_l = (const float*)d_in[9];
    const float* attn_r = (const float*)d_in[10];
    const float* b_gat  = (const float*)d_in[11];
    const float* W_fuse = (const float*)d_in[12];
    const float* b_fuse = (const float*)d_in[13];
    const float* W_gate = (const float*)d_in[14];
    const float* b_gate = (const float*)d_in[15];

    const int Nn = in_sizes[0] / D;
    const int E  = in_sizes[1];
    const int NR = Nn * R;
    const int NK = NR + Nn;

    cudaFuncSetAttribute(bf_gemm<1>, cudaFuncAttributeMaxDynamicSharedMemorySize, SMEM_BYTES);
    cudaFuncSetAttribute(bf_gemm<2>, cudaFuncAttributeMaxDynamicSharedMemorySize, SMEM_BYTES);
    cudaFuncSetAttribute(bf_gemm<3>, cudaFuncAttributeMaxDynamicSharedMemorySize, SMEM_BYTES);
    cudaFuncSetAttribute(bf_gemm<4>, cudaFuncAttributeMaxDynamicSharedMemorySize, SMEM_BYTES);
    cudaFuncSetAttribute(bf_gemm<5>, cudaFuncAttributeMaxDynamicSharedMemorySize, SMEM_BYTES);
    cudaFuncSetAttribute(bf_gemm<6>, cudaFuncAttributeMaxDynamicSharedMemorySize, SMEM_BYTES);

    float *hcat, *z, *el, *er, *tws;
    int *cnt, *off, *cur, *btot, *buf;
    __nv_bfloat16 *Ahi, *Alo, *Bhi_a, *Blo_a;
    uint32_t *whi, *wlo;
    cudaGetSymbolAddress((void**)&hcat, g_hcat);
    cudaGetSymbolAddress((void**)&z,    g_z);
    cudaGetSymbolAddress((void**)&el,   g_el);
    cudaGetSymbolAddress((void**)&er,   g_er);
    cudaGetSymbolAddress((void**)&tws,  g_twsum);
    cudaGetSymbolAddress((void**)&cnt,  g_cnt);
    cudaGetSymbolAddress((void**)&off,  g_off);
    cudaGetSymbolAddress((void**)&cur,  g_cur);
    cudaGetSymbolAddress((void**)&btot, g_btot);
    cudaGetSymbolAddress((void**)&buf,  g_buf);
    cudaGetSymbolAddress((void**)&Ahi,  g_ahi);
    cudaGetSymbolAddress((void**)&Alo,  g_alo);
    cudaGetSymbolAddress((void**)&Bhi_a, g_bhi);
    cudaGetSymbolAddress((void**)&Blo_a, g_blo);
    cudaGetSymbolAddress((void**)&whi,  g_wpk_hi);
    cudaGetSymbolAddress((void**)&wlo,  g_wpk_lo);

    const int MB = (Nn + 127) / 128;
    const int TPB = 256;
    const int e_blocks      = (E + TPB - 1) / TPB;
    const int nk_blocks     = (NK + TPB - 1) / TPB;
    const int nb            = (NK + 2047) / 2048;
    const int gat_blocks    = (Nn + 7) / 8;       // 8 warps per block
    const int cvt128_blocks = (Nn * D / 4 + TPB - 1) / TPB;
    const int cvt256_blocks = (Nn * 2 * D / 4 + TPB - 1) / TPB;

    // temporal mean
    zero_scalar_k<<<1, 1>>>(tws);
    reduce_sum_k<<<256, 256>>>(tw, tws, E);

    // CSR build (rel keys: s*R+r -> dst ; dst keys: NR+d -> src)
    zero_int_k<<<nk_blocks, TPB>>>(cnt, NK);
    hist_k<<<e_blocks, TPB>>>(src, dst, et, cnt, E, NR);
    scan1_k<<<nb, 256>>>(cnt, off, btot, NK);
    scan2_k<<<1, 256>>>(btot, nb);
    scan3_k<<<nk_blocks, TPB>>>(off, cur, btot, NK, 2 * E);
    fill_k<<<e_blocks, TPB>>>(src, dst, et, cur, buf, E, NR);

    // weights (once)
    cvt_wt_k<<<(3072 * 128 + TPB - 1) / TPB, TPB>>>(W_rel,  whi,              wlo,              3072);
    cvt_wt_k<<<(192 * 128 + TPB - 1) / TPB, TPB>>>(W_loop, whi + 3072 * 128, wlo + 3072 * 128, 192);
    cvt_wt_k<<<(192 * 128 + TPB - 1) / TPB, TPB>>>(W_gat,  whi + 3264 * 128, wlo + 3264 * 128, 192);
    cvt_wt_k<<<(128 * 128 + TPB - 1) / TPB, TPB>>>(W_fuse, whi + 3456 * 128, wlo + 3456 * 128, 128);
    cvt_wt_k<<<(64 * 128 + TPB - 1) / TPB, TPB>>>(W_gate, whi + 3584 * 128, wlo + 3584 * 128, 64);

    // layer-0 activations
    cvt_act_k<<<cvt128_blocks, TPB>>>(feat, Ahi, Alo, Nn * D / 4);

    __nv_bfloat16 *cur_hi = Ahi, *cur_lo = Alo;
    __nv_bfloat16 *oth_hi = Bhi_a, *oth_lo = Blo_a;

    for (int l = 0; l < NL; l++) {
        const float* brel_l = b_rel  + l * D;
        const float* bgat_l = b_gat  + l * D;
        const float* al_l   = attn_l + l * NH * DH;
        const float* ar_l   = attn_r + l * NH * DH;
        const uint32_t* wrel_hi  = whi + (long)(l * 1024) * 128;
        const uint32_t* wrel_lo  = wlo + (long)(l * 1024) * 128;
        const uint32_t* wloop_hi = whi + (long)(3072 + l * 64) * 128;
        const uint32_t* wloop_lo = wlo + (long)(3072 + l * 64) * 128;

        // 1) dual: y0 -> hcat[:,0:128] = X@W_loop + b_rel ; y1 -> z = X@W_gat (+ el/er)
        bf_gemm<5><<<dim3(MB, 2), 512, SMEM_BYTES>>>(
            cur_hi, cur_lo, D, wloop_hi, wloop_lo, (long)192 * 128,
            hcat, 2 * D, nullptr, nullptr,
            Nn, D, brel_l,
            z, el, er, al_l, ar_l,
            nullptr, nullptr, nullptr, nullptr, nullptr, nullptr, 0.f);

        // 2) rel GEMM with fused CSR scatter into hcat[:,0:128]
        bf_gemm<6><<<dim3(MB, R), 512, SMEM_BYTES>>>(
            cur_hi, cur_lo, D, wrel_hi, wrel_lo, 64 * 128,
            nullptr, 0, nullptr, nullptr,
            Nn, D, nullptr,
            nullptr, nullptr, nullptr, nullptr, nullptr,
            off, buf, hcat,
            nullptr, nullptr, nullptr, 0.f);

        // 3) GAT gather -> hcat[:,128:256] (atomic-free, includes softmax + b_gat)
        gat_gather_k<<<gat_blocks, TPB>>>(off, buf, el, er, z, bgat_l, hcat, Nn, NR);

        // 4) convert hcat
        cvt_act_k<<<cvt256_blocks, TPB>>>(hcat, oth_hi, oth_lo, Nn * 2 * D / 4);

        // 5) fuse (+ gate at layer 0)
        if (l == 0) {
            bf_gemm<3><<<dim3(MB, 1), 512, SMEM_BYTES>>>(
                oth_hi, oth_lo, 2 * D, whi + (long)3456 * 128, wlo + (long)3456 * 128, 0,
                z, D, cur_hi, cur_lo,
                Nn, 2 * D, b_fuse,
                nullptr, nullptr, nullptr, nullptr, nullptr,
                nullptr, nullptr, nullptr, nullptr, nullptr, nullptr, 0.f);
            bf_gemm<4><<<dim3(MB, 1), 512, SMEM_BYTES>>>(
                cur_hi, cur_lo, D, whi + (long)3584 * 128, wlo + (long)3584 * 128, 0,
                nullptr, 0, oth_hi, oth_lo,
                Nn, D, b_gate,
                nullptr, nullptr, nullptr, nullptr, nullptr,
                nullptr, nullptr, nullptr,
                z, W_gate + (long)D * D, tws, 1.0f / (float)E);
            __nv_bfloat16* t;
            t = cur_hi; cur_hi = oth_hi; oth_hi = t;
            t = cur_lo; cur_lo = oth_lo; oth_lo = t;
        } else if (l < NL - 1) {
            bf_gemm<2><<<dim3(MB, 1), 512, SMEM_BYTES>>>(
                oth_hi, oth_lo, 2 * D, whi + (long)3456 * 128, wlo + (long)3456 * 128, 0,
                nullptr, 0, cur_hi, cur_lo,
                Nn, 2 * D, b_fuse,
                nullptr, nullptr, nullptr, nullptr, nullptr,
                nullptr, nullptr, nullptr, nullptr, nullptr, nullptr, 0.f);
        } else {
            bf_gemm<1><<<dim3(MB, 1), 512, SMEM_BYTES>>>(
                oth_hi, oth_lo, 2 * D, whi + (long)3456 * 128, wlo + (long)3456 * 128, 0,
                (float*)d_out, D, nullptr, nullptr,
                Nn, 2 * D, b_fuse,
                nullptr, nullptr, nullptr, nullptr, nullptr,
                nullptr, nullptr, nullptr, nullptr, nullptr, nullptr, 0.f);
        }
    }
}

// round 6
// speedup vs baseline: 2.2346x; 1.0040x over previous
#include <cuda_runtime.h>
#include <cuda_bf16.h>
#include <math.h>
#include <stdint.h>

// Problem constants: N=30000, E=480000, D=128, R=16, H=4, DH=32, L=3
#define MAXN 30000
#define MAXE 480000
#define D 128
#define R 16
#define NH 4
#define DH 32
#define NL 3
#define NKMAX (MAXN * (R + 1))

// ---------------- scratch ----------------------------------------------------
__device__ float g_hcat[(long)MAXN * (2 * D)];
__device__ float g_z[(long)MAXN * D];
__device__ float g_el[MAXN * NH];
__device__ float g_er[MAXN * NH];
__device__ float g_twsum;
__device__ int g_cnt[NKMAX];
__device__ int g_off[NKMAX + 1];
__device__ int g_cur[NKMAX];
__device__ int g_btot[512];
__device__ int g_buf[2 * MAXE];
__device__ __nv_bfloat16 g_ahi[(long)MAXN * 256];
__device__ __nv_bfloat16 g_alo[(long)MAXN * 256];
__device__ __nv_bfloat16 g_bhi[(long)MAXN * 256];
__device__ __nv_bfloat16 g_blo[(long)MAXN * 256];
// packed bf16-pair weights (rows of 128 words, column-permuted):
//   [0,3072): W_rel (3 x 16 x 64)  [3072,3264): W_loop (3x64) [3264,3456): W_gat (3x64)
//   [3456,3584): W_fuse            [3584,3648): W_gate
#define WPK_ROWS 3648
__device__ uint32_t g_wpk_hi[WPK_ROWS * 128];
__device__ uint32_t g_wpk_lo[WPK_ROWS * 128];

// ---------------- helpers ----------------------------------------------------
__device__ __forceinline__ void red_add_v4(float* p, float x, float y, float z, float w) {
    asm volatile("red.global.add.v4.f32 [%0], {%1, %2, %3, %4};"
                 :: "l"(p), "f"(x), "f"(y), "f"(z), "f"(w) : "memory");
}
__device__ __forceinline__ void ldsm4(uint32_t r[4], uint32_t addr) {
    asm volatile("ldmatrix.sync.aligned.m8n8.x4.shared.b16 {%0,%1,%2,%3}, [%4];"
                 : "=r"(r[0]), "=r"(r[1]), "=r"(r[2]), "=r"(r[3]) : "r"(addr));
}
__device__ __forceinline__ void mma16816(float c[4], const uint32_t a[4], const uint32_t b[2]) {
    asm volatile("mma.sync.aligned.m16n8k16.row.col.f32.bf16.bf16.f32 "
                 "{%0,%1,%2,%3}, {%4,%5,%6,%7}, {%8,%9}, {%0,%1,%2,%3};"
                 : "+f"(c[0]), "+f"(c[1]), "+f"(c[2]), "+f"(c[3])
                 : "r"(a[0]), "r"(a[1]), "r"(a[2]), "r"(a[3]), "r"(b[0]), "r"(b[1]));
}
__device__ __forceinline__ void cp16(uint32_t dst, const void* src, bool pred) {
    int sz = pred ? 16 : 0;
    asm volatile("cp.async.cg.shared.global [%0], [%1], 16, %2;"
                 :: "r"(dst), "l"(src), "r"(sz));
}
__device__ __forceinline__ void cp_commit() { asm volatile("cp.async.commit_group;"); }
template <int NN> __device__ __forceinline__ void cp_wait() {
    asm volatile("cp.async.wait_group %0;" :: "n"(NN));
}

// ---------------- conversion kernels ------------------------------------------
__global__ void cvt_act_k(const float* __restrict__ x,
                          __nv_bfloat16* __restrict__ hi, __nv_bfloat16* __restrict__ lo,
                          int total4)
{
    int i = blockIdx.x * blockDim.x + threadIdx.x;
    if (i >= total4) return;
    float4 v = ((const float4*)x)[i];
    __nv_bfloat16 h0 = __float2bfloat16_rn(v.x), h1 = __float2bfloat16_rn(v.y);
    __nv_bfloat16 h2 = __float2bfloat16_rn(v.z), h3 = __float2bfloat16_rn(v.w);
    __nv_bfloat162 H0; H0.x = h0; H0.y = h1;
    __nv_bfloat162 H1; H1.x = h2; H1.y = h3;
    ((__nv_bfloat162*)hi)[i * 2 + 0] = H0;
    ((__nv_bfloat162*)hi)[i * 2 + 1] = H1;
    __nv_bfloat162 L0, L1;
    L0.x = __float2bfloat16_rn(v.x - __bfloat162float(h0));
    L0.y = __float2bfloat16_rn(v.y - __bfloat162float(h1));
    L1.x = __float2bfloat16_rn(v.z - __bfloat162float(h2));
    L1.y = __float2bfloat16_rn(v.w - __bfloat162float(h3));
    ((__nv_bfloat162*)lo)[i * 2 + 0] = L0;
    ((__nv_bfloat162*)lo)[i * 2 + 1] = L1;
}

__global__ void cvt_wt_k(const float* __restrict__ W,
                         uint32_t* __restrict__ hi, uint32_t* __restrict__ lo, int k2max)
{
    int i = blockIdx.x * blockDim.x + threadIdx.x;
    if (i >= k2max * 128) return;
    int k2 = i >> 7, n = i & 127;
    float a = W[(2 * k2) * 128 + n];
    float b = W[(2 * k2 + 1) * 128 + n];
    __nv_bfloat16 ah = __float2bfloat16_rn(a), bh = __float2bfloat16_rn(b);
    __nv_bfloat162 H; H.x = ah; H.y = bh;
    __nv_bfloat162 Lw;
    Lw.x = __float2bfloat16_rn(a - __bfloat162float(ah));
    Lw.y = __float2bfloat16_rn(b - __bfloat162float(bh));
    int np = (n & ~31) | ((n & 7) << 2) | ((n >> 3) & 3);
    hi[k2 * 128 + np] = *(uint32_t*)&H;
    lo[k2 * 128 + np] = *(uint32_t*)&Lw;
}

// ---------------- CSR build ----------------------------------------------------
__global__ void zero_int_k(int* p, int n) {
    int i = blockIdx.x * blockDim.x + threadIdx.x;
    if (i < n) p[i] = 0;
}
__global__ void hist_k(const int* __restrict__ src, const int* __restrict__ dst,
                       const int* __restrict__ et, int* __restrict__ cnt, int E, int NR)
{
    int e = blockIdx.x * blockDim.x + threadIdx.x;
    if (e >= E) return;
    atomicAdd(&cnt[src[e] * R + et[e]], 1);
    atomicAdd(&cnt[NR + dst[e]], 1);
}
__global__ void scan1_k(const int* __restrict__ cnt, int* __restrict__ off,
                        int* __restrict__ btot, int n)
{
    __shared__ int ws[8];
    int t = threadIdx.x;
    int base = blockIdx.x * 2048 + t * 8;
    int v[8], s = 0;
#pragma unroll
    for (int i = 0; i < 8; i++) {
        int x = (base + i < n) ? cnt[base + i] : 0;
        v[i] = s; s += x;
    }
    int lane = t & 31, w = t >> 5;
    int inc = s;
#pragma unroll
    for (int o = 1; o < 32; o <<= 1) {
        int y = __shfl_up_sync(0xFFFFFFFFu, inc, o);
        if (lane >= o) inc += y;
    }
    if (lane == 31) ws[w] = inc;
    int texc = inc - s;
    __syncthreads();
    int wbase = 0;
#pragma unroll
    for (int i = 0; i < 8; i++) wbase += (i < w) ? ws[i] : 0;
#pragma unroll
    for (int i = 0; i < 8; i++)
        if (base + i < n) off[base + i] = wbase + texc + v[i];
    if (t == 255) btot[blockIdx.x] = wbase + inc;
}
__global__ void scan2_k(int* btot, int nb) {
    __shared__ int ws[8];
    int t = threadIdx.x;
    int xv = (t < nb) ? btot[t] : 0;
    int lane = t & 31, w = t >> 5;
    int inc = xv;
#pragma unroll
    for (int o = 1; o < 32; o <<= 1) {
        int y = __shfl_up_sync(0xFFFFFFFFu, inc, o);
        if (lane >= o) inc += y;
    }
    if (lane == 31) ws[w] = inc;
    __syncthreads();
    int wbase = 0;
#pragma unroll
    for (int i = 0; i < 8; i++) wbase += (i < w) ? ws[i] : 0;
    if (t < nb) btot[t] = wbase + inc - xv;
}
__global__ void scan3_k(int* __restrict__ off, int* __restrict__ cur,
                        const int* __restrict__ btot, int n, int total)
{
    int i = blockIdx.x * blockDim.x + threadIdx.x;
    if (i < n) {
        int o = off[i] + btot[i >> 11];
        off[i] = o; cur[i] = o;
    }
    if (i == 0) off[n] = total;
}
__global__ void fill_k(const int* __restrict__ src, const int* __restrict__ dst,
                       const int* __restrict__ et, int* __restrict__ cur,
                       int* __restrict__ buf, int E, int NR)
{
    int e = blockIdx.x * blockDim.x + threadIdx.x;
    if (e >= E) return;
    int s = src[e], d = dst[e];
    int p1 = atomicAdd(&cur[s * R + et[e]], 1);
    buf[p1] = d;
    int p2 = atomicAdd(&cur[NR + d], 1);
    buf[p2] = s;
}

// ---------------- bf16x3 tensor-core GEMM -------------------------------------
// MODE: 1 bias+relu->fp32 | 2 bias+relu->bf16 | 3 bias->fp32+bf16 |
//       4 temporal gate->bf16 | 5 dual (y0 bias->C; y1 z + el/er) |
//       7 rel x2: two relations per CTA, CSR scatter via paired red.v4
#define AS_BUF 8192
#define BS_BUF 8704
#define OFF_AHI 0
#define OFF_ALO (2 * AS_BUF)
#define OFF_B5  (4 * AS_BUF)
#define SMEM_STD (4 * AS_BUF + 4 * BS_BUF)   // modes 1-5: 67584
#define SMEM_REL (4 * AS_BUF + 8 * BS_BUF)   // mode 7:   102400

template <int MODE>
__global__ __launch_bounds__(512)
void bf_gemm(const __nv_bfloat16* __restrict__ Ahi, const __nv_bfloat16* __restrict__ Alo,
             int lda,
             const uint32_t* __restrict__ Bhi, const uint32_t* __restrict__ Blo, long bstr,
             float* __restrict__ C, int ldc,
             __nv_bfloat16* __restrict__ obhi, __nv_bfloat16* __restrict__ oblo,
             int M, int K,
             const float* __restrict__ bias,
             float* __restrict__ zout, float* __restrict__ el, float* __restrict__ er,
             const float* __restrict__ attnl, const float* __restrict__ attnr,
             const int* __restrict__ csr_off, const int* __restrict__ csr_buf,
             float* __restrict__ hcat,
             const float* __restrict__ hcsrc, const float* __restrict__ gate_wlast,
             const float* __restrict__ tw_sum, float invE)
{
    extern __shared__ char sm[];
    const uint32_t smB = (uint32_t)__cvta_generic_to_shared(sm);
    constexpr int NREL = (MODE == 7) ? 2 : 1;

    const uint32_t* BhY = Bhi + (long)blockIdx.y * (NREL * bstr);
    const uint32_t* BlY = Blo + (long)blockIdx.y * (NREL * bstr);

    const int m0   = blockIdx.x * 128;
    const int tid  = threadIdx.x;
    const int lane = tid & 31;
    const int wid  = tid >> 5;
    const int grp  = lane >> 2;
    const int tig  = lane & 3;
    const int wm   = (wid >> 2) * 32;
    const int wn   = (wid & 3) * 32;

    const int aRow = tid >> 2;
    const int aC   = tid & 3;
    const int aSC  = aC ^ ((aRow >> 1) & 3);
    const int gmA  = m0 + aRow;
    const bool aOk = gmA < M;
    const long aSrcOff = (long)(aOk ? gmA : 0) * lda + aC * 8;
    const uint32_t aDst = aRow * 64 + aSC * 16;
    const int bRow = tid >> 5;
    const int bC   = tid & 31;
    const uint32_t bDst = bRow * 544 + bC * 16;
    const int bSrcOff = bRow * 128 + bC * 4;

    // B smem offsets: [buf][rel][hi/lo]
    auto offB = [&](int b, int rel, int hl) -> uint32_t {
        return OFF_B5 + (uint32_t)(((b * NREL + rel) * 2 + hl) * BS_BUF);
    };

    auto issue = [&](int k0, int b) {
        cp16(smB + OFF_AHI + b * AS_BUF + aDst, Ahi + aSrcOff + k0, aOk);
        cp16(smB + OFF_ALO + b * AS_BUF + aDst, Alo + aSrcOff + k0, aOk);
#pragma unroll
        for (int rel = 0; rel < NREL; rel++) {
            cp16(smB + offB(b, rel, 0) + bDst, BhY + rel * bstr + (k0 >> 1) * 128 + bSrcOff, true);
            cp16(smB + offB(b, rel, 1) + bDst, BlY + rel * bstr + (k0 >> 1) * 128 + bSrcOff, true);
        }
        cp_commit();
    };

    float acc[NREL][2][4][4];
#pragma unroll
    for (int r = 0; r < NREL; r++)
#pragma unroll
        for (int i = 0; i < 2; i++)
#pragma unroll
            for (int j = 0; j < 4; j++)
#pragma unroll
                for (int k = 0; k < 4; k++) acc[r][i][j][k] = 0.f;

    const int arow_l  = wm + (lane & 15);
    const int aShift  = (arow_l >> 1) & 3;
    const int aChunk0 = lane >> 4;
    const uint32_t aRowByte = arow_l * 64;

    const int nch = K >> 5;
    issue(0, 0);

    for (int c = 0; c < nch; c++) {
        const int b = c & 1;
        if (c + 1 < nch) issue((c + 1) << 5, b ^ 1);
        if (c + 1 < nch) cp_wait<1>(); else cp_wait<0>();
        __syncthreads();

#pragma unroll
        for (int kc = 0; kc < 2; kc++) {
            uint32_t ah[2][4], al[2][4];
#pragma unroll
            for (int mt = 0; mt < 2; mt++) {
                const int sc = ((kc * 2 + aChunk0) ^ aShift) * 16;
                uint32_t off = aRowByte + mt * 1024 + sc;
                ldsm4(ah[mt], smB + OFF_AHI + b * AS_BUF + off);
                ldsm4(al[mt], smB + OFF_ALO + b * AS_BUF + off);
            }
            const int r0 = kc * 8 + tig;
            const uint32_t bo0 = (uint32_t)((r0 * 136 + wn + grp * 4) << 2);
            const uint32_t bo1 = (uint32_t)(((r0 + 4) * 136 + wn + grp * 4) << 2);
#pragma unroll
            for (int rel = 0; rel < NREL; rel++) {
                const char* bsH = sm + offB(b, rel, 0);
                const char* bsL = sm + offB(b, rel, 1);
                uint4 h0 = *(const uint4*)(bsH + bo0);
                uint4 h1 = *(const uint4*)(bsH + bo1);
                uint4 l0 = *(const uint4*)(bsL + bo0);
                uint4 l1 = *(const uint4*)(bsL + bo1);
                uint32_t bh[4][2], bl[4][2];
                bh[0][0] = h0.x; bh[1][0] = h0.y; bh[2][0] = h0.z; bh[3][0] = h0.w;
                bh[0][1] = h1.x; bh[1][1] = h1.y; bh[2][1] = h1.z; bh[3][1] = h1.w;
                bl[0][0] = l0.x; bl[1][0] = l0.y; bl[2][0] = l0.z; bl[3][0] = l0.w;
                bl[0][1] = l1.x; bl[1][1] = l1.y; bl[2][1] = l1.z; bl[3][1] = l1.w;
#pragma unroll
                for (int mt = 0; mt < 2; mt++)
#pragma unroll
                    for (int nt = 0; nt < 4; nt++) {
                        mma16816(acc[rel][mt][nt], ah[mt], bh[nt]);
                        mma16816(acc[rel][mt][nt], al[mt], bh[nt]);
                        mma16816(acc[rel][mt][nt], ah[mt], bl[nt]);
                    }
            }
        }
        __syncthreads();
    }

    // ================= epilogues =================
    if (MODE == 7) {
        const int g4   = (tig >> 1) * 4;           // quad column base within octet
        const int ntb  = (tig & 1) * 2;            // this lane handles nt = ntb, ntb+1
#pragma unroll
        for (int rel = 0; rel < NREL; rel++) {
            const int rY = blockIdx.y * NREL + rel;
#pragma unroll
            for (int mt = 0; mt < 2; mt++)
#pragma unroll
                for (int half = 0; half < 2; half++) {
                    const int gm = m0 + wm + mt * 16 + grp + half * 8;
                    // pair exchange (uniform: before any gm-divergent branch)
                    float q[4][4];
#pragma unroll
                    for (int nt = 0; nt < 4; nt++) {
                        float v0 = acc[rel][mt][nt][half * 2 + 0];
                        float v1 = acc[rel][mt][nt][half * 2 + 1];
                        float o0 = __shfl_xor_sync(0xFFFFFFFFu, v0, 1);
                        float o1 = __shfl_xor_sync(0xFFFFFFFFu, v1, 1);
                        if ((tig & 1) == 0) { q[nt][0] = v0; q[nt][1] = v1; q[nt][2] = o0; q[nt][3] = o1; }
                        else                { q[nt][0] = o0; q[nt][1] = o1; q[nt][2] = v0; q[nt][3] = v1; }
                    }
                    if (gm >= M) continue;
                    const int key = gm * R + rY;
                    const int e0 = csr_off[key], e1 = csr_off[key + 1];
                    for (int e = e0; e < e1; e++) {
                        const int d = csr_buf[e];
                        float* basep = hcat + (long)d * 256 + wn + g4;
                        red_add_v4(basep + ntb * 8,
                                   q[ntb][0], q[ntb][1], q[ntb][2], q[ntb][3]);
                        red_add_v4(basep + (ntb + 1) * 8,
                                   q[ntb + 1][0], q[ntb + 1][1], q[ntb + 1][2], q[ntb + 1][3]);
                    }
                }
        }
        return;
    }

    if (MODE == 5 && blockIdx.y == 1) {
        const int h = wid & 3;
#pragma unroll
        for (int mt = 0; mt < 2; mt++)
#pragma unroll
            for (int half = 0; half < 2; half++) {
                const int gm = m0 + wm + mt * 16 + grp + half * 8;
                const bool ok = gm < M;
                float elp = 0.f, erp = 0.f;
#pragma unroll
                for (int nt = 0; nt < 4; nt++) {
                    const int n = wn + nt * 8 + 2 * tig;
                    float v0 = acc[0][mt][nt][half * 2 + 0];
                    float v1 = acc[0][mt][nt][half * 2 + 1];
                    if (ok) {
                        float2 o; o.x = v0; o.y = v1;
                        *(float2*)(zout + (long)gm * 128 + n) = o;
                    }
                    const int dh = nt * 8 + 2 * tig;
                    elp += v0 * attnl[h * 32 + dh] + v1 * attnl[h * 32 + dh + 1];
                    erp += v0 * attnr[h * 32 + dh] + v1 * attnr[h * 32 + dh + 1];
                }
                elp += __shfl_xor_sync(0xFFFFFFFFu, elp, 1);
                elp += __shfl_xor_sync(0xFFFFFFFFu, elp, 2);
                erp += __shfl_xor_sync(0xFFFFFFFFu, erp, 1);
                erp += __shfl_xor_sync(0xFFFFFFFFu, erp, 2);
                if (ok && tig == 0) {
                    el[gm * NH + h] = elp;
                    er[gm * NH + h] = erp;
                }
            }
        return;
    }

    float twm = 0.0f;
    if (MODE == 4) twm = tw_sum[0] * invE;

#pragma unroll
    for (int mt = 0; mt < 2; mt++)
#pragma unroll
        for (int nt = 0; nt < 4; nt++) {
            const int n = wn + nt * 8 + 2 * tig;
#pragma unroll
            for (int half = 0; half < 2; half++) {
                const int gm = m0 + wm + mt * 16 + grp + half * 8;
                if (gm >= M) continue;
                float v0 = acc[0][mt][nt][half * 2 + 0];
                float v1 = acc[0][mt][nt][half * 2 + 1];
                if (bias) { v0 += bias[n]; v1 += bias[n + 1]; }
                if (MODE == 1 || MODE == 2) { v0 = fmaxf(v0, 0.f); v1 = fmaxf(v1, 0.f); }
                if (MODE == 4) {
                    float g0 = v0 + twm * gate_wlast[n];
                    float g1 = v1 + twm * gate_wlast[n + 1];
                    g0 = 1.0f / (1.0f + expf(-g0));
                    g1 = 1.0f / (1.0f + expf(-g1));
                    float2 hc = *(const float2*)(hcsrc + (long)gm * 128 + n);
                    v0 = fmaxf(hc.x * g0, 0.f);
                    v1 = fmaxf(hc.y * g1, 0.f);
                }
                if (MODE == 1 || MODE == 3 || MODE == 5) {
                    float2 o; o.x = v0; o.y = v1;
                    *(float2*)(C + (long)gm * ldc + n) = o;
                }
                if (MODE == 2 || MODE == 3 || MODE == 4) {
                    __nv_bfloat162 H, Lw;
                    H.x = __float2bfloat16_rn(v0);
                    H.y = __float2bfloat16_rn(v1);
                    Lw.x = __float2bfloat16_rn(v0 - __bfloat162float(H.x));
                    Lw.y = __float2bfloat16_rn(v1 - __bfloat162float(H.y));
                    *(__nv_bfloat162*)(obhi + (long)gm * 128 + n) = H;
                    *(__nv_bfloat162*)(oblo + (long)gm * 128 + n) = Lw;
                }
            }
        }
}

// ---------------- GAT gather (atomic-free, unroll x2) -----------------------------
__global__ void gat_gather_k(const int* __restrict__ off, const int* __restrict__ buf,
                             const float* __restrict__ el, const float* __restrict__ er,
                             const float* __restrict__ z, const float* __restrict__ bgat,
                             float* __restrict__ hcat, int n, int NR)
{
    int node = (blockIdx.x * blockDim.x + threadIdx.x) >> 5;
    if (node >= n) return;
    int lane = threadIdx.x & 31;
    int d0 = lane * 4;
    int head = lane >> 3;
    int e0 = off[NR + node], e1 = off[NR + node + 1];
    float erv = er[node * NH + head];
    float ax0 = 0.f, ay0 = 0.f, az0 = 0.f, aw0 = 0.f, sx0 = 0.f;
    float ax1 = 0.f, ay1 = 0.f, az1 = 0.f, aw1 = 0.f, sx1 = 0.f;
    int j = e0;
    for (; j + 1 < e1; j += 2) {
        int s0 = buf[j], s1 = buf[j + 1];
        float v0 = el[s0 * NH + head] + erv;
        float v1 = el[s1 * NH + head] + erv;
        v0 = (v0 >= 0.f) ? v0 : 0.2f * v0;
        v1 = (v1 >= 0.f) ? v1 : 0.2f * v1;
        float ex0 = __expf(v0), ex1 = __expf(v1);
        float4 z0 = *(const float4*)(z + (long)s0 * 128 + d0);
        float4 z1 = *(const float4*)(z + (long)s1 * 128 + d0);
        sx0 += ex0; sx1 += ex1;
        ax0 = fmaf(ex0, z0.x, ax0); ay0 = fmaf(ex0, z0.y, ay0);
        az0 = fmaf(ex0, z0.z, az0); aw0 = fmaf(ex0, z0.w, aw0);
        ax1 = fmaf(ex1, z1.x, ax1); ay1 = fmaf(ex1, z1.y, ay1);
        az1 = fmaf(ex1, z1.z, az1); aw1 = fmaf(ex1, z1.w, aw1);
    }
    if (j < e1) {
        int s0 = buf[j];
        float v0 = el[s0 * NH + head] + erv;
        v0 = (v0 >= 0.f) ? v0 : 0.2f * v0;
        float ex0 = __expf(v0);
        float4 z0 = *(const float4*)(z + (long)s0 * 128 + d0);
        sx0 += ex0;
        ax0 = fmaf(ex0, z0.x, ax0); ay0 = fmaf(ex0, z0.y, ay0);
        az0 = fmaf(ex0, z0.z, az0); aw0 = fmaf(ex0, z0.w, aw0);
    }
    float sx = sx0 + sx1;
    float inv = (e1 > e0) ? (1.0f / sx) : 0.0f;
    float4 bg = *(const float4*)(bgat + d0);
    float4 o;
    o.x = fmaf(ax0 + ax1, inv, bg.x); o.y = fmaf(ay0 + ay1, inv, bg.y);
    o.z = fmaf(az0 + az1, inv, bg.z); o.w = fmaf(aw0 + aw1, inv, bg.w);
    *(float4*)(hcat + (long)node * 256 + 128 + d0) = o;
}

// ---------------- misc ------------------------------------------------------------
__global__ void zero_scalar_k(float* p) { *p = 0.0f; }
__global__ void reduce_sum_k(const float* __restrict__ x, float* out, int n) {
    float s = 0.0f;
    for (int i = blockIdx.x * blockDim.x + threadIdx.x; i < n; i += gridDim.x * blockDim.x)
        s += x[i];
#pragma unroll
    for (int o = 16; o > 0; o >>= 1) s += __shfl_xor_sync(0xFFFFFFFFu, s, o);
    __shared__ float ws[8];
    if ((threadIdx.x & 31) == 0) ws[threadIdx.x >> 5] = s;
    __syncthreads();
    if (threadIdx.x < 32) {
        s = (threadIdx.x < (blockDim.x >> 5)) ? ws[threadIdx.x] : 0.0f;
#pragma unroll
        for (int o = 4; o > 0; o >>= 1) s += __shfl_xor_sync(0xFFFFFFFFu, s, o);
        if (threadIdx.x == 0) atomicAdd(out, s);
    }
}

// ---------------- launcher ----------------------------------------------------------
extern "C" void kernel_launch(void* const* d_in, const int* in_sizes, int n_in,
                              void* d_out, int out_size)
{
    const float* feat   = (const float*)d_in[0];
    const int*   src    = (const int*)  d_in[1];
    const int*   dst    = (const int*)  d_in[2];
    const int*   et     = (const int*)  d_in[3];
    const float* tw     = (const float*)d_in[4];
    const float* W_rel  = (const float*)d_in[5];
    const float* b_rel  = (const float*)d_in[6];
    const float* W_loop = (const float*)d_in[7];
    const float* W_gat  = (const float*)d_in[8];
    const float* attn_l = (const float*)d_in[9];
    const float* attn_r = (const float*)d_in[10];
    const float* b_gat  = (const float*)d_in[11];
    const float* W_fuse = (const float*)d_in[12];
    const float* b_fuse = (const float*)d_in[13];
    const float* W_gate = (const float*)d_in[14];
    const float* b_gate = (const float*)d_in[15];

    const int Nn = in_sizes[0] / D;
    const int E  = in_sizes[1];
    const int NR = Nn * R;
    const int NK = NR + Nn;

    cudaFuncSetAttribute(bf_gemm<1>, cudaFuncAttributeMaxDynamicSharedMemorySize, SMEM_STD);
    cudaFuncSetAttribute(bf_gemm<2>, cudaFuncAttributeMaxDynamicSharedMemorySize, SMEM_STD);
    cudaFuncSetAttribute(bf_gemm<3>, cudaFuncAttributeMaxDynamicSharedMemorySize, SMEM_STD);
    cudaFuncSetAttribute(bf_gemm<4>, cudaFuncAttributeMaxDynamicSharedMemorySize, SMEM_STD);
    cudaFuncSetAttribute(bf_gemm<5>, cudaFuncAttributeMaxDynamicSharedMemorySize, SMEM_STD);
    cudaFuncSetAttribute(bf_gemm<7>, cudaFuncAttributeMaxDynamicSharedMemorySize, SMEM_REL);

    float *hcat, *z, *el, *er, *tws;
    int *cnt, *off, *cur, *btot, *buf;
    __nv_bfloat16 *Ahi, *Alo, *Bhi_a, *Blo_a;
    uint32_t *whi, *wlo;
    cudaGetSymbolAddress((void**)&hcat, g_hcat);
    cudaGetSymbolAddress((void**)&z,    g_z);
    cudaGetSymbolAddress((void**)&el,   g_el);
    cudaGetSymbolAddress((void**)&er,   g_er);
    cudaGetSymbolAddress((void**)&tws,  g_twsum);
    cudaGetSymbolAddress((void**)&cnt,  g_cnt);
    cudaGetSymbolAddress((void**)&off,  g_off);
    cudaGetSymbolAddress((void**)&cur,  g_cur);
    cudaGetSymbolAddress((void**)&btot, g_btot);
    cudaGetSymbolAddress((void**)&buf,  g_buf);
    cudaGetSymbolAddress((void**)&Ahi,  g_ahi);
    cudaGetSymbolAddress((void**)&Alo,  g_alo);
    cudaGetSymbolAddress((void**)&Bhi_a, g_bhi);
    cudaGetSymbolAddress((void**)&Blo_a, g_blo);
    cudaGetSymbolAddress((void**)&whi,  g_wpk_hi);
    cudaGetSymbolAddress((void**)&wlo,  g_wpk_lo);

    const int MB = (Nn + 127) / 128;
    const int TPB = 256;
    const int e_blocks      = (E + TPB - 1) / TPB;
    const int nk_blocks     = (NK + TPB - 1) / TPB;
    const int nb            = (NK + 2047) / 2048;
    const int gat_blocks    = (Nn + 7) / 8;
    const int cvt128_blocks = (Nn * D / 4 + TPB - 1) / TPB;
    const int cvt256_blocks = (Nn * 2 * D / 4 + TPB - 1) / TPB;

    zero_scalar_k<<<1, 1>>>(tws);
    reduce_sum_k<<<256, 256>>>(tw, tws, E);

    zero_int_k<<<nk_blocks, TPB>>>(cnt, NK);
    hist_k<<<e_blocks, TPB>>>(src, dst, et, cnt, E, NR);
    scan1_k<<<nb, 256>>>(cnt, off, btot, NK);
    scan2_k<<<1, 256>>>(btot, nb);
    scan3_k<<<nk_blocks, TPB>>>(off, cur, btot, NK, 2 * E);
    fill_k<<<e_blocks, TPB>>>(src, dst, et, cur, buf, E, NR);

    cvt_wt_k<<<(3072 * 128 + TPB - 1) / TPB, TPB>>>(W_rel,  whi,              wlo,              3072);
    cvt_wt_k<<<(192 * 128 + TPB - 1) / TPB, TPB>>>(W_loop, whi + 3072 * 128, wlo + 3072 * 128, 192);
    cvt_wt_k<<<(192 * 128 + TPB - 1) / TPB, TPB>>>(W_gat,  whi + 3264 * 128, wlo + 3264 * 128, 192);
    cvt_wt_k<<<(128 * 128 + TPB - 1) / TPB, TPB>>>(W_fuse, whi + 3456 * 128, wlo + 3456 * 128, 128);
    cvt_wt_k<<<(64 * 128 + TPB - 1) / TPB, TPB>>>(W_gate, whi + 3584 * 128, wlo + 3584 * 128, 64);

    cvt_act_k<<<cvt128_blocks, TPB>>>(feat, Ahi, Alo, Nn * D / 4);

    __nv_bfloat16 *cur_hi = Ahi, *cur_lo = Alo;
    __nv_bfloat16 *oth_hi = Bhi_a, *oth_lo = Blo_a;

    for (int l = 0; l < NL; l++) {
        const float* brel_l = b_rel  + l * D;
        const float* bgat_l = b_gat  + l * D;
        const float* al_l   = attn_l + l * NH * DH;
        const float* ar_l   = attn_r + l * NH * DH;
        const uint32_t* wrel_hi  = whi + (long)(l * 1024) * 128;
        const uint32_t* wrel_lo  = wlo + (long)(l * 1024) * 128;
        const uint32_t* wloop_hi = whi + (long)(3072 + l * 64) * 128;
        const uint32_t* wloop_lo = wlo + (long)(3072 + l * 64) * 128;

        // 1) dual GEMM: y0 -> hcat[:,0:128] = X@W_loop + b_rel ; y1 -> z + el/er
        bf_gemm<5><<<dim3(MB, 2), 512, SMEM_STD>>>(
            cur_hi, cur_lo, D, wloop_hi, wloop_lo, (long)192 * 128,
            hcat, 2 * D, nullptr, nullptr,
            Nn, D, brel_l,
            z, el, er, al_l, ar_l,
            nullptr, nullptr, nullptr, nullptr, nullptr, nullptr, 0.f);

        // 2) rel GEMM, 2 relations per CTA, fused CSR scatter
        bf_gemm<7><<<dim3(MB, R / 2), 512, SMEM_REL>>>(
            cur_hi, cur_lo, D, wrel_hi, wrel_lo, 64 * 128,
            nullptr, 0, nullptr, nullptr,
            Nn, D, nullptr,
            nullptr, nullptr, nullptr, nullptr, nullptr,
            off, buf, hcat,
            nullptr, nullptr, nullptr, 0.f);

        // 3) GAT gather -> hcat[:,128:256]
        gat_gather_k<<<gat_blocks, TPB>>>(off, buf, el, er, z, bgat_l, hcat, Nn, NR);

        // 4) convert hcat
        cvt_act_k<<<cvt256_blocks, TPB>>>(hcat, oth_hi, oth_lo, Nn * 2 * D / 4);

        // 5) fuse (+ gate at layer 0)
        if (l == 0) {
            bf_gemm<3><<<dim3(MB, 1), 512, SMEM_STD>>>(
                oth_hi, oth_lo, 2 * D, whi + (long)3456 * 128, wlo + (long)3456 * 128, 0,
                z, D, cur_hi, cur_lo,
                Nn, 2 * D, b_fuse,
                nullptr, nullptr, nullptr, nullptr, nullptr,
                nullptr, nullptr, nullptr, nullptr, nullptr, nullptr, 0.f);
            bf_gemm<4><<<dim3(MB, 1), 512, SMEM_STD>>>(
                cur_hi, cur_lo, D, whi + (long)3584 * 128, wlo + (long)3584 * 128, 0,
                nullptr, 0, oth_hi, oth_lo,
                Nn, D, b_gate,
                nullptr, nullptr, nullptr, nullptr, nullptr,
                nullptr, nullptr, nullptr,
                z, W_gate + (long)D * D, tws, 1.0f / (float)E);
            __nv_bfloat16* t;
            t = cur_hi; cur_hi = oth_hi; oth_hi = t;
            t = cur_lo; cur_lo = oth_lo; oth_lo = t;
        } else if (l < NL - 1) {
            bf_gemm<2><<<dim3(MB, 1), 512, SMEM_STD>>>(
                oth_hi, oth_lo, 2 * D, whi + (long)3456 * 128, wlo + (long)3456 * 128, 0,
                nullptr, 0, cur_hi, cur_lo,
                Nn, 2 * D, b_fuse,
                nullptr, nullptr, nullptr, nullptr, nullptr,
                nullptr, nullptr, nullptr, nullptr, nullptr, nullptr, 0.f);
        } else {
            bf_gemm<1><<<dim3(MB, 1), 512, SMEM_STD>>>(
                oth_hi, oth_lo, 2 * D, whi + (long)3456 * 128, wlo + (long)3456 * 128, 0,
                (float*)d_out, D, nullptr, nullptr,
                Nn, 2 * D, b_fuse,
                nullptr, nullptr, nullptr, nullptr, nullptr,
                nullptr, nullptr, nullptr, nullptr, nullptr, nullptr, 0.f);
        }
    }
}